// round 5
// baseline (speedup 1.0000x reference)
#include <cuda_runtime.h>
#include <math.h>

#define N_NODES 512
#define DIM 128
#define NA 192          // total anchors
#define G3 384          // 3*DIM
typedef unsigned long long ULL;

// ---------------- scratch (no allocations allowed) ----------------
__device__ float g_x[N_NODES * DIM];
__device__ float g_abn[N_NODES];
__device__ float g_tpos[N_NODES];
__device__ float g_Gi[6 * N_NODES * G3];
__device__ float g_hout[NA * 2 * DIM];
__device__ float g_abnout[NA * 2];
__device__ float g_WihT[6 * DIM * G3];   // [sd][k][row]
__device__ float g_WhhT[6 * DIM * G3];   // [sd][k][row]
__device__ int   g_quads[48][4];         // [scale*16+quad][4 anchor ids], len-matched

__device__ __forceinline__ float sigf(float x) { return 1.f / (1.f + __expf(-x)); }
__device__ __forceinline__ float tanhfast(float x) { return 2.f / (1.f + __expf(-2.f * x)) - 1.f; }

// ---------------- kernel 1: preprocess ----------------
__global__ void k_pre(const float* __restrict__ emb, const float* __restrict__ tp,
                      const float* __restrict__ pred, const float* __restrict__ al_p,
                      const float* __restrict__ kern)
{
    int tid = blockIdx.x * blockDim.x + threadIdx.x;
    if (tid < N_NODES * DIM) {
        int n = tid >> 7, d = tid & 127;
        float freq = (10.f / 127.f) * (float)d;
        g_x[tid] = emb[tid] + 0.05f * sinf(tp[n] * freq);
    }
    if (tid < N_NODES) {
        int n = tid;
        float kv[5];
        #pragma unroll
        for (int k = 0; k < 5; k++) kv[k] = kern[k];
        float sv[5];
        #pragma unroll
        for (int c = 0; c < 5; c++) {
            float acc = 0.f;
            #pragma unroll
            for (int k = 0; k < 5; k++) {
                int nn = n + k - 2;
                if (nn >= 0 && nn < N_NODES) acc += kv[k] * pred[nn * 5 + c];
            }
            sv[c] = acc;
        }
        float m = sv[0];
        #pragma unroll
        for (int c = 1; c < 5; c++) m = fmaxf(m, sv[c]);
        float den = 0.f;
        #pragma unroll
        for (int c = 0; c < 5; c++) den += __expf(sv[c] - m);
        g_abn[n] = __expf(sv[0] - m) / den;
        g_tpos[n] = tp[n] * al_p[0];
    }
}

// ---------------- kernel 2: tiled transpose of GRU weights (coalesced both sides) ----------------
// grid (48, 6): bx -> (ktile 0..3, rtile 0..11), by = sd. block (32,8).
__global__ void k_tr(const float* __restrict__ Wih, const float* __restrict__ Whh)
{
    __shared__ float s1[32][33];
    __shared__ float s2[32][33];
    int sd = blockIdx.y;
    int ktile = blockIdx.x & 3, rtile = blockIdx.x >> 2;
    int x = threadIdx.x, y = threadIdx.y;
    size_t base = (size_t)sd * G3 * DIM;
    #pragma unroll
    for (int j = 0; j < 4; j++) {
        int r = rtile * 32 + y * 4 + j;
        s1[y * 4 + j][x] = Wih[base + (size_t)r * DIM + ktile * 32 + x];
        s2[y * 4 + j][x] = Whh[base + (size_t)r * DIM + ktile * 32 + x];
    }
    __syncthreads();
    size_t obase = (size_t)sd * DIM * G3;
    #pragma unroll
    for (int j = 0; j < 4; j++) {
        int k = ktile * 32 + y * 4 + j;
        g_WihT[obase + (size_t)k * G3 + rtile * 32 + x] = s1[x][y * 4 + j];
        g_WhhT[obase + (size_t)k * G3 + rtile * 32 + x] = s2[x][y * 4 + j];
    }
}

// ---------------- kernel 3: Gi precompute (weights in regs, nodes streamed) + rank block ----------------
// grid (16, 7): y<6 -> sd, x = 32-node chunk. y==6,x==0 -> anchor quad ranking.
__global__ __launch_bounds__(384) void k_gi(const float* __restrict__ bih,
                                            const float* __restrict__ anchors)
{
    int t = threadIdx.x;
    if (blockIdx.y == 6) {
        if (blockIdx.x != 0) return;
        __shared__ float tps[N_NODES];
        __shared__ int lens[NA];
        for (int i = t; i < N_NODES; i += 384) tps[i] = g_tpos[i];
        __syncthreads();
        if (t < NA) {
            float stt = anchors[2 * t], enn = anchors[2 * t + 1];
            int c = 0;
            for (int n = 0; n < N_NODES; n++)
                c += (tps[n] >= stt && tps[n] <= enn) ? 1 : 0;
            lens[t] = c;
        }
        __syncthreads();
        if (t < NA) {
            int s = t >> 6;
            int L = lens[t];
            int r = 0;
            for (int j = 0; j < 64; j++) {
                int Lj = lens[s * 64 + j];
                if (Lj > L || (Lj == L && s * 64 + j < t)) r++;
            }
            g_quads[s * 16 + (r >> 2)][r & 3] = t;
        }
        return;
    }

    int sd = blockIdx.y, chunk = blockIdx.x;
    __shared__ __align__(16) float sx[32 * DIM];
    const float4* src = (const float4*)(g_x + (size_t)chunk * 32 * DIM);
    for (int i = t; i < 32 * DIM / 4; i += 384) ((float4*)sx)[i] = src[i];

    const float* wt = g_WihT + (size_t)sd * DIM * G3 + t;
    ULL w[64];
    #pragma unroll
    for (int k = 0; k < 64; k++) {
        float w0 = wt[(size_t)(2 * k) * G3];
        float w1 = wt[(size_t)(2 * k + 1) * G3];
        asm("mov.b64 %0,{%1,%2};" : "=l"(w[k]) : "f"(w0), "f"(w1));
    }
    float b = bih[sd * G3 + t];
    unsigned xb;
    asm("{.reg .u64 t0; cvta.to.shared.u64 t0,%1; cvt.u32.u64 %0,t0;}" : "=r"(xb) : "l"((float*)sx));
    __syncthreads();

    float* outp = g_Gi + ((size_t)sd * N_NODES + chunk * 32) * G3 + t;
    float zf = 0.f;
    for (int n = 0; n < 32; n++) {
        ULL acA, acB;
        asm("mov.b64 %0,{%1,%2};" : "=l"(acA) : "f"(b), "f"(zf));
        asm("mov.b64 %0,{%1,%2};" : "=l"(acB) : "f"(zf), "f"(zf));
        unsigned base = xb + n * 512;
        #pragma unroll
        for (int i = 0; i < 16; i++) {
            ULL p0, p1, p2, p3;
            asm volatile("ld.shared.v2.b64 {%0,%1},[%2];" : "=l"(p0), "=l"(p1) : "r"(base + i * 32));
            asm volatile("ld.shared.v2.b64 {%0,%1},[%2];" : "=l"(p2), "=l"(p3) : "r"(base + i * 32 + 16));
            asm("fma.rn.f32x2 %0,%1,%2,%0;" : "+l"(acA) : "l"(w[4 * i])     , "l"(p0));
            asm("fma.rn.f32x2 %0,%1,%2,%0;" : "+l"(acB) : "l"(w[4 * i + 1]) , "l"(p1));
            asm("fma.rn.f32x2 %0,%1,%2,%0;" : "+l"(acA) : "l"(w[4 * i + 2]) , "l"(p2));
            asm("fma.rn.f32x2 %0,%1,%2,%0;" : "+l"(acB) : "l"(w[4 * i + 3]) , "l"(p3));
        }
        float a0, a1, b0, b1;
        asm("mov.b64 {%0,%1},%2;" : "=f"(a0), "=f"(a1) : "l"(acA));
        asm("mov.b64 {%0,%1},%2;" : "=f"(b0), "=f"(b1) : "l"(acB));
        outp[(size_t)n * G3] = (a0 + a1) + (b0 + b1);
    }
}

// ---------------- kernel 4: GRU recurrence, 4 len-matched anchors per block ----------------
// grid 96: bx -> scale (bx>>5), quad ((bx&31)>>1), dir (bx&1). Single wave.
__global__ __launch_bounds__(384) void k_gru(const float* __restrict__ anchors,
                                             const float* __restrict__ bhh,
                                             const float* __restrict__ aWih,
                                             const float* __restrict__ aWhh,
                                             const float* __restrict__ abih,
                                             const float* __restrict__ abhh)
{
    int t = threadIdx.x;
    int scale = blockIdx.x >> 5;
    int rem = blockIdx.x & 31;
    int quad = rem >> 1, dir = rem & 1;
    int sd = scale * 2 + dir;

    __shared__ __align__(16) float sh_h[4][DIM];
    __shared__ float sh_gh[4][G3];
    __shared__ unsigned short idx[4][N_NODES];
    __shared__ int sh_len[4];
    __shared__ float sh_abh[4];
    __shared__ float aw[12];
    __shared__ int sh_aid[4];

    if (t < 4) sh_aid[t] = g_quads[scale * 16 + quad][t];
    __syncthreads();

    int wid = t >> 5, lane = t & 31;
    if (wid < 4) {                       // warp q compacts anchor q (and pre-reverses for dir=1)
        int aa = sh_aid[wid];
        float stt = anchors[2 * aa], enn = anchors[2 * aa + 1];
        unsigned short* ix = idx[wid];
        int off = 0;
        for (int base = 0; base < N_NODES; base += 32) {
            int n = base + lane;
            float tp = g_tpos[n];
            bool m = (tp >= stt) && (tp <= enn);
            unsigned bal = __ballot_sync(0xffffffffu, m);
            if (m) ix[off + __popc(bal & ((1u << lane) - 1u))] = (unsigned short)n;
            off += __popc(bal);
        }
        if (dir) {                       // reverse in place
            for (int i = lane; i < (off >> 1); i += 32) {
                unsigned short tmp = ix[i];
                ix[i] = ix[off - 1 - i];
                ix[off - 1 - i] = tmp;
            }
        }
        if (lane == 0) { sh_len[wid] = off; sh_abh[wid] = 0.f; }
    }
    if (t < DIM) { sh_h[0][t] = 0.f; sh_h[1][t] = 0.f; sh_h[2][t] = 0.f; sh_h[3][t] = 0.f; }
    if (t >= 160 && t < 163) {
        int j = t - 160, base = sd * 3;
        aw[j]     = aWih[base + j];
        aw[3 + j] = aWhh[base + j];
        aw[6 + j] = abih[base + j];
        aw[9 + j] = abhh[base + j];
    }

    // Whh row t -> registers (f32x2-packed k-pairs, coalesced loads from WhhT)
    const float* wt = g_WhhT + (size_t)sd * DIM * G3 + t;
    ULL w[64];
    #pragma unroll
    for (int k = 0; k < 64; k++) {
        float w0 = wt[(size_t)(2 * k) * G3];
        float w1 = wt[(size_t)(2 * k + 1) * G3];
        asm("mov.b64 %0,{%1,%2};" : "=l"(w[k]) : "f"(w0), "f"(w1));
    }
    float bh = bhh[sd * G3 + t];
    float zf = 0.f;

    unsigned hb;
    asm("{.reg .u64 t0; cvta.to.shared.u64 t0,%1; cvt.u32.u64 %0,t0;}" : "=r"(hb) : "l"(&sh_h[0][0]));
    __syncthreads();

    int len0 = sh_len[0], len1 = sh_len[1], len2 = sh_len[2], len3 = sh_len[3];
    int L01 = len0 > len1 ? len0 : len1;
    int L23 = len2 > len3 ? len2 : len3;
    int L = L01 > L23 ? L01 : L23;
    const float* Gi = g_Gi + (size_t)sd * N_NODES * G3;

    int myq = (t < 128) ? 0 : ((t < 256) ? 1 : 2);
    int mylen = (t < 128) ? len0 : ((t < 256) ? len1 : len2);
    int tt = t & 127;
    int abln = 0;
    if (t < 4) abln = (t == 0) ? len0 : ((t == 1) ? len1 : ((t == 2) ? len2 : len3));

    for (int step = 0; step < L; step++) {
        // prefetch input gates (overlap with dot)
        float gA0 = 0.f, gA1 = 0.f, gA2 = 0.f;
        float gB0 = 0.f, gB1 = 0.f, gB2 = 0.f;
        float abin = 0.f;
        bool actm = step < mylen;
        bool act3 = step < len3;
        if (actm) {
            const float* gp = Gi + (size_t)idx[myq][step] * G3;
            gA0 = gp[tt]; gA1 = gp[DIM + tt]; gA2 = gp[2 * DIM + tt];
        }
        if (t < 128 && act3) {
            const float* gp = Gi + (size_t)idx[3][step] * G3;
            gB0 = gp[tt]; gB1 = gp[DIM + tt]; gB2 = gp[2 * DIM + tt];
        }
        if (t < 4 && step < abln) abin = g_abn[idx[t][step]];

        // dot: gh[q][t] = Whh_row_t . h_q + bh, 4 anchors share the weights
        ULL ac0, ac1, ac2, ac3;
        asm("mov.b64 %0,{%1,%2};" : "=l"(ac0) : "f"(bh), "f"(zf));
        asm("mov.b64 %0,{%1,%2};" : "=l"(ac1) : "f"(bh), "f"(zf));
        asm("mov.b64 %0,{%1,%2};" : "=l"(ac2) : "f"(bh), "f"(zf));
        asm("mov.b64 %0,{%1,%2};" : "=l"(ac3) : "f"(bh), "f"(zf));
        #pragma unroll
        for (int i = 0; i < 32; i++) {
            ULL h0a, h0b, h1a, h1b, h2a, h2b, h3a, h3b;
            asm volatile("ld.shared.v2.b64 {%0,%1},[%2];" : "=l"(h0a), "=l"(h0b) : "r"(hb + i * 16));
            asm volatile("ld.shared.v2.b64 {%0,%1},[%2];" : "=l"(h1a), "=l"(h1b) : "r"(hb + 512 + i * 16));
            asm("fma.rn.f32x2 %0,%1,%2,%0;" : "+l"(ac0) : "l"(w[2 * i])     , "l"(h0a));
            asm("fma.rn.f32x2 %0,%1,%2,%0;" : "+l"(ac0) : "l"(w[2 * i + 1]) , "l"(h0b));
            asm("fma.rn.f32x2 %0,%1,%2,%0;" : "+l"(ac1) : "l"(w[2 * i])     , "l"(h1a));
            asm("fma.rn.f32x2 %0,%1,%2,%0;" : "+l"(ac1) : "l"(w[2 * i + 1]) , "l"(h1b));
            asm volatile("ld.shared.v2.b64 {%0,%1},[%2];" : "=l"(h2a), "=l"(h2b) : "r"(hb + 1024 + i * 16));
            asm volatile("ld.shared.v2.b64 {%0,%1},[%2];" : "=l"(h3a), "=l"(h3b) : "r"(hb + 1536 + i * 16));
            asm("fma.rn.f32x2 %0,%1,%2,%0;" : "+l"(ac2) : "l"(w[2 * i])     , "l"(h2a));
            asm("fma.rn.f32x2 %0,%1,%2,%0;" : "+l"(ac2) : "l"(w[2 * i + 1]) , "l"(h2b));
            asm("fma.rn.f32x2 %0,%1,%2,%0;" : "+l"(ac3) : "l"(w[2 * i])     , "l"(h3a));
            asm("fma.rn.f32x2 %0,%1,%2,%0;" : "+l"(ac3) : "l"(w[2 * i + 1]) , "l"(h3b));
        }
        {
            float p0, p1;
            asm("mov.b64 {%0,%1},%2;" : "=f"(p0), "=f"(p1) : "l"(ac0));
            sh_gh[0][t] = p0 + p1;
            asm("mov.b64 {%0,%1},%2;" : "=f"(p0), "=f"(p1) : "l"(ac1));
            sh_gh[1][t] = p0 + p1;
            asm("mov.b64 {%0,%1},%2;" : "=f"(p0), "=f"(p1) : "l"(ac2));
            sh_gh[2][t] = p0 + p1;
            asm("mov.b64 {%0,%1},%2;" : "=f"(p0), "=f"(p1) : "l"(ac3));
            sh_gh[3][t] = p0 + p1;
        }
        __syncthreads();

        // gates
        if (actm) {
            const float* gh = sh_gh[myq];
            float r  = sigf(gA0 + gh[tt]);
            float z  = sigf(gA1 + gh[DIM + tt]);
            float nn = tanhfast(gA2 + r * gh[2 * DIM + tt]);
            sh_h[myq][tt] = (1.f - z) * nn + z * sh_h[myq][tt];
        }
        if (t < 128 && act3) {
            const float* gh = sh_gh[3];
            float r  = sigf(gB0 + gh[tt]);
            float z  = sigf(gB1 + gh[DIM + tt]);
            float nn = tanhfast(gB2 + r * gh[2 * DIM + tt]);
            sh_h[3][tt] = (1.f - z) * nn + z * sh_h[3][tt];
        }
        if (t < 4 && step < abln) {
            float h = sh_abh[t];
            float r  = sigf(aw[0] * abin + aw[6] + aw[3] * h + aw[9]);
            float z  = sigf(aw[1] * abin + aw[7] + aw[4] * h + aw[10]);
            float nn = tanhfast(aw[2] * abin + aw[8] + r * (aw[5] * h + aw[11]));
            sh_abh[t] = (1.f - z) * nn + z * h;
        }
        __syncthreads();
    }

    // outputs
    {
        int am = sh_aid[myq];
        g_hout[((size_t)am * 2 + dir) * DIM + tt] = sh_h[myq][tt];
        if (t < 128) {
            int a3 = sh_aid[3];
            g_hout[((size_t)a3 * 2 + dir) * DIM + tt] = sh_h[3][tt];
        }
        if (t < 4) g_abnout[sh_aid[t] * 2 + dir] = sh_abh[t];
    }
}

// ---------------- kernel 5: per-anchor MLP head, 8-way ILP ----------------
__global__ __launch_bounds__(256) void k_head(const float* __restrict__ anchors,
                                              const float* __restrict__ al_p,
                                              const float* __restrict__ W1, const float* __restrict__ b1,
                                              const float* __restrict__ W2, const float* __restrict__ b2,
                                              const float* __restrict__ W3, const float* __restrict__ b3,
                                              const float* __restrict__ start_w,
                                              const float* __restrict__ end_w,
                                              float* __restrict__ out)
{
    int a = blockIdx.x;
    int s = a >> 6;
    int t = threadIdx.x;
    const int FIN = 2 * DIM + 3;   // 259
    const int FOUT = 47;

    __shared__ float sf[FIN + 1];
    __shared__ float h1[256];
    __shared__ float h2[256];
    __shared__ float o[FOUT];
    __shared__ float soeo[2];

    float al = al_p[0];
    if (t < DIM) {
        sf[t]       = g_hout[((size_t)a * 2 + 0) * DIM + t];
        sf[DIM + t] = g_hout[((size_t)a * 2 + 1) * DIM + t];
    }
    if (t == 0) {
        sf[256] = 0.5f * (g_abnout[a * 2] + g_abnout[a * 2 + 1]);
        float stt = anchors[a * 2], enn = anchors[a * 2 + 1];
        sf[257] = (stt + enn) * 0.5f / al;
        sf[258] = (enn - stt) / al;
    }
    __syncthreads();

    {
        const float* W = W1 + (size_t)s * FIN * 256 + t;
        float acc[8];
        #pragma unroll
        for (int j = 0; j < 8; j++) acc[j] = 0.f;
        for (int i = 0; i < 256; i += 8) {
            #pragma unroll
            for (int j = 0; j < 8; j++) acc[j] += W[(size_t)(i + j) * 256] * sf[i + j];
        }
        acc[0] += W[(size_t)256 * 256] * sf[256];
        acc[1] += W[(size_t)257 * 256] * sf[257];
        acc[2] += W[(size_t)258 * 256] * sf[258];
        float r = (((acc[0] + acc[1]) + (acc[2] + acc[3])) + ((acc[4] + acc[5]) + (acc[6] + acc[7])))
                  + b1[s * 256 + t];
        h1[t] = fmaxf(r, 0.f);
    }
    __syncthreads();

    {
        const float* W = W2 + (size_t)s * 256 * 256 + t;
        float acc[8];
        #pragma unroll
        for (int j = 0; j < 8; j++) acc[j] = 0.f;
        for (int i = 0; i < 256; i += 8) {
            #pragma unroll
            for (int j = 0; j < 8; j++) acc[j] += W[(size_t)(i + j) * 256] * h1[i + j];
        }
        float r = (((acc[0] + acc[1]) + (acc[2] + acc[3])) + ((acc[4] + acc[5]) + (acc[6] + acc[7])))
                  + b2[s * 256 + t];
        h2[t] = fmaxf(r, 0.f);
    }
    __syncthreads();

    if (t < FOUT) {
        const float* W = W3 + (size_t)s * 256 * FOUT + t;
        float acc[8];
        #pragma unroll
        for (int j = 0; j < 8; j++) acc[j] = 0.f;
        for (int i = 0; i < 256; i += 8) {
            #pragma unroll
            for (int j = 0; j < 8; j++) acc[j] += W[(size_t)(i + j) * FOUT] * h2[i + j];
        }
        o[t] = (((acc[0] + acc[1]) + (acc[2] + acc[3])) + ((acc[4] + acc[5]) + (acc[6] + acc[7])))
               + b3[s * FOUT + t];
    }
    __syncthreads();

    if (t < 2) {
        const float* wv = (t == 0) ? (start_w + s * 21) : (end_w + s * 21);
        const float* ov = o + t * 21;
        float m = -1e30f;
        for (int j = 0; j < 21; j++) m = fmaxf(m, ov[j]);
        float den = 0.f, num = 0.f;
        for (int j = 0; j < 21; j++) { float e = __expf(ov[j] - m); den += e; num += e * wv[j]; }
        soeo[t] = num / den;
    }
    __syncthreads();

    if (t == 0) {
        float stt = anchors[a * 2], enn = anchors[a * 2 + 1];
        out[a * 2]      = fminf(fmaxf(stt + soeo[0], 0.f), al);
        out[a * 2 + 1]  = fminf(fmaxf(enn + soeo[1], 0.f), al);
        out[2 * NA + a] = o[42];
    }
    if (t < 4) out[3 * NA + a * 4 + t] = o[43 + t];
}

// ---------------- launcher ----------------
extern "C" void kernel_launch(void* const* d_in, const int* in_sizes, int n_in,
                              void* d_out, int out_size)
{
    const float* emb   = (const float*)d_in[0];
    const float* tp    = (const float*)d_in[1];
    const float* pred  = (const float*)d_in[2];
    const float* al_p  = (const float*)d_in[3];
    const float* anc   = (const float*)d_in[4];
    const float* kern  = (const float*)d_in[5];
    const float* fWih  = (const float*)d_in[6];
    const float* fWhh  = (const float*)d_in[7];
    const float* fbih  = (const float*)d_in[8];
    const float* fbhh  = (const float*)d_in[9];
    const float* aWih  = (const float*)d_in[10];
    const float* aWhh  = (const float*)d_in[11];
    const float* abih  = (const float*)d_in[12];
    const float* abhh  = (const float*)d_in[13];
    const float* sw    = (const float*)d_in[14];
    const float* ew    = (const float*)d_in[15];
    const float* W1    = (const float*)d_in[16];
    const float* b1    = (const float*)d_in[17];
    const float* W2    = (const float*)d_in[18];
    const float* b2    = (const float*)d_in[19];
    const float* W3    = (const float*)d_in[20];
    const float* b3    = (const float*)d_in[21];
    float* outp = (float*)d_out;

    k_pre<<<(N_NODES * DIM + 255) / 256, 256>>>(emb, tp, pred, al_p, kern);
    k_tr<<<dim3(48, 6), dim3(32, 8)>>>(fWih, fWhh);
    k_gi<<<dim3(16, 7), 384>>>(fbih, anc);
    k_gru<<<96, 384>>>(anc, fbhh, aWih, aWhh, abih, abhh);
    k_head<<<NA, 256>>>(anc, al_p, W1, b1, W2, b2, W3, b3, sw, ew, outp);
}

// round 6
// speedup vs baseline: 1.2655x; 1.2655x over previous
#include <cuda_runtime.h>
#include <math.h>

#define N_NODES 512
#define DIM 128
#define NA 192          // total anchors
#define G3 384          // 3*DIM
typedef unsigned long long ULL;

// ---------------- scratch (no allocations allowed) ----------------
__device__ float g_x[N_NODES * DIM];
__device__ float g_abn[N_NODES];
__device__ float g_tpos[N_NODES];
__device__ float g_Gi[6 * N_NODES * G3];
__device__ float g_hout[NA * 2 * DIM];
__device__ float g_abnout[NA * 2];
__device__ float g_WihT[6 * DIM * G3];   // [sd][k][row]
__device__ float g_WhhT[6 * DIM * G3];   // [sd][k][row]
__device__ int   g_perm[NA * 2];         // task schedule, len desc (task = a*2+dir)

__device__ __forceinline__ float sigf(float x) { return 1.f / (1.f + __expf(-x)); }
__device__ __forceinline__ float tanhfast(float x) { return 2.f / (1.f + __expf(-2.f * x)) - 1.f; }

// ---------------- kernel 1: preprocess ----------------
__global__ void k_pre(const float* __restrict__ emb, const float* __restrict__ tp,
                      const float* __restrict__ pred, const float* __restrict__ al_p,
                      const float* __restrict__ kern)
{
    int tid = blockIdx.x * blockDim.x + threadIdx.x;
    if (tid < N_NODES * DIM) {
        int n = tid >> 7, d = tid & 127;
        float freq = (10.f / 127.f) * (float)d;
        g_x[tid] = emb[tid] + 0.05f * sinf(tp[n] * freq);
    }
    if (tid < N_NODES) {
        int n = tid;
        float kv[5];
        #pragma unroll
        for (int k = 0; k < 5; k++) kv[k] = kern[k];
        float sv[5];
        #pragma unroll
        for (int c = 0; c < 5; c++) {
            float acc = 0.f;
            #pragma unroll
            for (int k = 0; k < 5; k++) {
                int nn = n + k - 2;
                if (nn >= 0 && nn < N_NODES) acc += kv[k] * pred[nn * 5 + c];
            }
            sv[c] = acc;
        }
        float m = sv[0];
        #pragma unroll
        for (int c = 1; c < 5; c++) m = fmaxf(m, sv[c]);
        float den = 0.f;
        #pragma unroll
        for (int c = 0; c < 5; c++) den += __expf(sv[c] - m);
        g_abn[n] = __expf(sv[0] - m) / den;
        g_tpos[n] = tp[n] * al_p[0];
    }
}

// ---------------- kernel 2: tiled transpose of GRU weights ----------------
__global__ void k_tr(const float* __restrict__ Wih, const float* __restrict__ Whh)
{
    __shared__ float s1[32][33];
    __shared__ float s2[32][33];
    int sd = blockIdx.y;
    int ktile = blockIdx.x & 3, rtile = blockIdx.x >> 2;
    int x = threadIdx.x, y = threadIdx.y;
    size_t base = (size_t)sd * G3 * DIM;
    #pragma unroll
    for (int j = 0; j < 4; j++) {
        int r = rtile * 32 + y * 4 + j;
        s1[y * 4 + j][x] = Wih[base + (size_t)r * DIM + ktile * 32 + x];
        s2[y * 4 + j][x] = Whh[base + (size_t)r * DIM + ktile * 32 + x];
    }
    __syncthreads();
    size_t obase = (size_t)sd * DIM * G3;
    #pragma unroll
    for (int j = 0; j < 4; j++) {
        int k = ktile * 32 + y * 4 + j;
        g_WihT[obase + (size_t)k * G3 + rtile * 32 + x] = s1[x][y * 4 + j];
        g_WhhT[obase + (size_t)k * G3 + rtile * 32 + x] = s2[x][y * 4 + j];
    }
}

// ---------------- kernel 3: Gi precompute (16-node chunks) + schedule rank ----------------
// grid (32, 7): y<6 -> sd, x = 16-node chunk. y==6,x==0 -> task ranking by length.
__global__ __launch_bounds__(384) void k_gi(const float* __restrict__ bih,
                                            const float* __restrict__ anchors)
{
    int t = threadIdx.x;
    if (blockIdx.y == 6) {
        if (blockIdx.x != 0) return;
        __shared__ float tps[N_NODES];
        __shared__ int lens[NA];
        for (int i = t; i < N_NODES; i += 384) tps[i] = g_tpos[i];
        __syncthreads();
        if (t < NA) {
            float stt = anchors[2 * t], enn = anchors[2 * t + 1];
            int c = 0;
            for (int n = 0; n < N_NODES; n++)
                c += (tps[n] >= stt && tps[n] <= enn) ? 1 : 0;
            lens[t] = c;
        }
        __syncthreads();
        if (t < NA) {
            int L = lens[t];
            int r = 0;
            for (int j = 0; j < NA; j++) {
                int Lj = lens[j];
                if (Lj > L || (Lj == L && j < t)) r++;
            }
            g_perm[2 * r]     = 2 * t;       // (anchor t, fwd)
            g_perm[2 * r + 1] = 2 * t + 1;   // (anchor t, bwd)
        }
        return;
    }

    int sd = blockIdx.y, chunk = blockIdx.x;
    __shared__ __align__(16) float sx[16 * DIM];
    const float4* src = (const float4*)(g_x + (size_t)chunk * 16 * DIM);
    for (int i = t; i < 16 * DIM / 4; i += 384) ((float4*)sx)[i] = src[i];

    const float* wt = g_WihT + (size_t)sd * DIM * G3 + t;
    ULL w[64];
    #pragma unroll
    for (int k = 0; k < 64; k++) {
        float w0 = wt[(size_t)(2 * k) * G3];
        float w1 = wt[(size_t)(2 * k + 1) * G3];
        asm("mov.b64 %0,{%1,%2};" : "=l"(w[k]) : "f"(w0), "f"(w1));
    }
    float b = bih[sd * G3 + t];
    unsigned xb;
    asm("{.reg .u64 t0; cvta.to.shared.u64 t0,%1; cvt.u32.u64 %0,t0;}" : "=r"(xb) : "l"((float*)sx));
    __syncthreads();

    float* outp = g_Gi + ((size_t)sd * N_NODES + chunk * 16) * G3 + t;
    float zf = 0.f;
    for (int n = 0; n < 16; n++) {
        ULL acA, acB;
        asm("mov.b64 %0,{%1,%2};" : "=l"(acA) : "f"(b), "f"(zf));
        asm("mov.b64 %0,{%1,%2};" : "=l"(acB) : "f"(zf), "f"(zf));
        unsigned base = xb + n * 512;
        #pragma unroll
        for (int i = 0; i < 16; i++) {
            ULL p0, p1, p2, p3;
            asm volatile("ld.shared.v2.b64 {%0,%1},[%2];" : "=l"(p0), "=l"(p1) : "r"(base + i * 32));
            asm volatile("ld.shared.v2.b64 {%0,%1},[%2];" : "=l"(p2), "=l"(p3) : "r"(base + i * 32 + 16));
            asm("fma.rn.f32x2 %0,%1,%2,%0;" : "+l"(acA) : "l"(w[4 * i])     , "l"(p0));
            asm("fma.rn.f32x2 %0,%1,%2,%0;" : "+l"(acB) : "l"(w[4 * i + 1]) , "l"(p1));
            asm("fma.rn.f32x2 %0,%1,%2,%0;" : "+l"(acA) : "l"(w[4 * i + 2]) , "l"(p2));
            asm("fma.rn.f32x2 %0,%1,%2,%0;" : "+l"(acB) : "l"(w[4 * i + 3]) , "l"(p3));
        }
        float a0, a1, b0, b1;
        asm("mov.b64 {%0,%1},%2;" : "=f"(a0), "=f"(a1) : "l"(acA));
        asm("mov.b64 {%0,%1},%2;" : "=f"(b0), "=f"(b1) : "l"(acB));
        outp[(size_t)n * G3] = (a0 + a1) + (b0 + b1);
    }
}

// ---------------- kernel 4: GRU recurrence, 768 threads, half-row weights ----------------
// One (anchor,dir) per block; thread (hf, r): half hf of Whh row r. 24 warps resident.
__global__ __launch_bounds__(768, 1) void k_gru(const float* __restrict__ anchors,
                                                const float* __restrict__ bhh,
                                                const float* __restrict__ aWih,
                                                const float* __restrict__ aWhh,
                                                const float* __restrict__ abih,
                                                const float* __restrict__ abhh)
{
    int t = threadIdx.x;
    int hf = t >> 8 >> 1;              // t/512? no: computed below properly
    hf = (t >= 384) ? 1 : 0;
    int r = t - hf * 384;              // row 0..383

    __shared__ int sh_task;
    __shared__ __align__(16) float sh_h[DIM];
    __shared__ float sh_part[2 * G3];
    __shared__ unsigned short idx[N_NODES];
    __shared__ int sh_len;
    __shared__ float sh_abh;
    __shared__ float aw[12];

    if (t == 0) sh_task = g_perm[blockIdx.x];
    __syncthreads();
    int task = sh_task;
    int a = task >> 1, dir = task & 1;
    int sd = (a >> 6) * 2 + dir;

    int wid = t >> 5, lane = t & 31;
    if (wid == 0) {                     // warp 0: compact node list, reverse if bwd
        float stt = anchors[2 * a], enn = anchors[2 * a + 1];
        int off = 0;
        for (int base = 0; base < N_NODES; base += 32) {
            int n = base + lane;
            float tp = g_tpos[n];
            bool m = (tp >= stt) && (tp <= enn);
            unsigned bal = __ballot_sync(0xffffffffu, m);
            if (m) idx[off + __popc(bal & ((1u << lane) - 1u))] = (unsigned short)n;
            off += __popc(bal);
        }
        if (dir) {
            for (int i = lane; i < (off >> 1); i += 32) {
                unsigned short tmp = idx[i];
                idx[i] = idx[off - 1 - i];
                idx[off - 1 - i] = tmp;
            }
        }
        if (lane == 0) { sh_len = off; sh_abh = 0.f; }
    }
    if (t >= 32 && t < 44) {            // abn GRU weights
        int j = (t - 32) % 3, grp = (t - 32) / 3, base = sd * 3;
        const float* srcs[4] = { aWih, aWhh, abih, abhh };
        aw[grp * 3 + j] = srcs[grp][base + j];
    }
    if (t >= 64 && t < 64 + DIM) sh_h[t - 64] = 0.f;

    // half-row weights: 32 f32x2 pairs, k in [hf*64, hf*64+64)
    const float* wt = g_WhhT + (size_t)sd * DIM * G3 + (size_t)(hf * 64) * G3 + r;
    ULL w[32];
    #pragma unroll
    for (int j = 0; j < 32; j++) {
        float w0 = wt[(size_t)(2 * j) * G3];
        float w1 = wt[(size_t)(2 * j + 1) * G3];
        asm("mov.b64 %0,{%1,%2};" : "=l"(w[j]) : "f"(w0), "f"(w1));
    }
    float bh = (hf == 0) ? bhh[sd * G3 + r] : 0.f;
    float zf = 0.f;

    unsigned hb;
    asm("{.reg .u64 t0; cvta.to.shared.u64 t0,%1; cvt.u32.u64 %0,t0;}" : "=r"(hb) : "l"((float*)sh_h));
    hb += hf * 256;                      // this half reads bytes [hf*256, hf*256+256)
    __syncthreads();

    int len = sh_len;
    const float* Gi = g_Gi + (size_t)sd * N_NODES * G3;
    int po = hf * G3 + r;                // partial slot

    for (int step = 0; step < len; step++) {
        // prefetch input gates / abn input (overlaps the dot)
        float gi0 = 0.f, gi1 = 0.f, gi2 = 0.f, abin = 0.f;
        if (t < DIM) {
            const float* gp = Gi + (size_t)idx[step] * G3;
            gi0 = gp[t]; gi1 = gp[DIM + t]; gi2 = gp[2 * DIM + t];
        } else if (t == DIM) {
            abin = g_abn[idx[step]];
        }

        // half-dot: 2 interleaved chains of 16
        ULL a0, a1;
        asm("mov.b64 %0,{%1,%2};" : "=l"(a0) : "f"(bh), "f"(zf));
        asm("mov.b64 %0,{%1,%2};" : "=l"(a1) : "f"(zf), "f"(zf));
        #pragma unroll
        for (int j = 0; j < 16; j++) {
            ULL p0, p1;
            asm volatile("ld.shared.v2.b64 {%0,%1},[%2];" : "=l"(p0), "=l"(p1) : "r"(hb + j * 16));
            asm("fma.rn.f32x2 %0,%1,%2,%0;" : "+l"(a0) : "l"(w[2 * j])     , "l"(p0));
            asm("fma.rn.f32x2 %0,%1,%2,%0;" : "+l"(a1) : "l"(w[2 * j + 1]) , "l"(p1));
        }
        float p0f, p1f, p2f, p3f;
        asm("mov.b64 {%0,%1},%2;" : "=f"(p0f), "=f"(p1f) : "l"(a0));
        asm("mov.b64 {%0,%1},%2;" : "=f"(p2f), "=f"(p3f) : "l"(a1));
        sh_part[po] = (p0f + p1f) + (p2f + p3f);
        __syncthreads();

        if (t < DIM) {
            float ghr = sh_part[t]           + sh_part[G3 + t];
            float ghz = sh_part[DIM + t]     + sh_part[G3 + DIM + t];
            float ghn = sh_part[2 * DIM + t] + sh_part[G3 + 2 * DIM + t];
            float rr = sigf(gi0 + ghr);
            float zz = sigf(gi1 + ghz);
            float nn = tanhfast(gi2 + rr * ghn);
            sh_h[t] = (1.f - zz) * nn + zz * sh_h[t];
        } else if (t == DIM) {
            float h = sh_abh;
            float rr = sigf(aw[0] * abin + aw[6] + aw[3] * h + aw[9]);
            float zz = sigf(aw[1] * abin + aw[7] + aw[4] * h + aw[10]);
            float nn = tanhfast(aw[2] * abin + aw[8] + rr * (aw[5] * h + aw[11]));
            sh_abh = (1.f - zz) * nn + zz * h;
        }
        __syncthreads();
    }

    if (t < DIM) g_hout[((size_t)a * 2 + dir) * DIM + t] = sh_h[t];
    if (t == DIM) g_abnout[a * 2 + dir] = sh_abh;
}

// ---------------- kernel 5: per-anchor MLP head, 8-way ILP ----------------
__global__ __launch_bounds__(256) void k_head(const float* __restrict__ anchors,
                                              const float* __restrict__ al_p,
                                              const float* __restrict__ W1, const float* __restrict__ b1,
                                              const float* __restrict__ W2, const float* __restrict__ b2,
                                              const float* __restrict__ W3, const float* __restrict__ b3,
                                              const float* __restrict__ start_w,
                                              const float* __restrict__ end_w,
                                              float* __restrict__ out)
{
    int a = blockIdx.x;
    int s = a >> 6;
    int t = threadIdx.x;
    const int FIN = 2 * DIM + 3;   // 259
    const int FOUT = 47;

    __shared__ float sf[FIN + 1];
    __shared__ float h1[256];
    __shared__ float h2[256];
    __shared__ float o[FOUT];
    __shared__ float soeo[2];

    float al = al_p[0];
    if (t < DIM) {
        sf[t]       = g_hout[((size_t)a * 2 + 0) * DIM + t];
        sf[DIM + t] = g_hout[((size_t)a * 2 + 1) * DIM + t];
    }
    if (t == 0) {
        sf[256] = 0.5f * (g_abnout[a * 2] + g_abnout[a * 2 + 1]);
        float stt = anchors[a * 2], enn = anchors[a * 2 + 1];
        sf[257] = (stt + enn) * 0.5f / al;
        sf[258] = (enn - stt) / al;
    }
    __syncthreads();

    {
        const float* W = W1 + (size_t)s * FIN * 256 + t;
        float acc[8];
        #pragma unroll
        for (int j = 0; j < 8; j++) acc[j] = 0.f;
        for (int i = 0; i < 256; i += 8) {
            #pragma unroll
            for (int j = 0; j < 8; j++) acc[j] += W[(size_t)(i + j) * 256] * sf[i + j];
        }
        acc[0] += W[(size_t)256 * 256] * sf[256];
        acc[1] += W[(size_t)257 * 256] * sf[257];
        acc[2] += W[(size_t)258 * 256] * sf[258];
        float r = (((acc[0] + acc[1]) + (acc[2] + acc[3])) + ((acc[4] + acc[5]) + (acc[6] + acc[7])))
                  + b1[s * 256 + t];
        h1[t] = fmaxf(r, 0.f);
    }
    __syncthreads();

    {
        const float* W = W2 + (size_t)s * 256 * 256 + t;
        float acc[8];
        #pragma unroll
        for (int j = 0; j < 8; j++) acc[j] = 0.f;
        for (int i = 0; i < 256; i += 8) {
            #pragma unroll
            for (int j = 0; j < 8; j++) acc[j] += W[(size_t)(i + j) * 256] * h1[i + j];
        }
        float r = (((acc[0] + acc[1]) + (acc[2] + acc[3])) + ((acc[4] + acc[5]) + (acc[6] + acc[7])))
                  + b2[s * 256 + t];
        h2[t] = fmaxf(r, 0.f);
    }
    __syncthreads();

    if (t < FOUT) {
        const float* W = W3 + (size_t)s * 256 * FOUT + t;
        float acc[8];
        #pragma unroll
        for (int j = 0; j < 8; j++) acc[j] = 0.f;
        for (int i = 0; i < 256; i += 8) {
            #pragma unroll
            for (int j = 0; j < 8; j++) acc[j] += W[(size_t)(i + j) * FOUT] * h2[i + j];
        }
        o[t] = (((acc[0] + acc[1]) + (acc[2] + acc[3])) + ((acc[4] + acc[5]) + (acc[6] + acc[7])))
               + b3[s * FOUT + t];
    }
    __syncthreads();

    if (t < 2) {
        const float* wv = (t == 0) ? (start_w + s * 21) : (end_w + s * 21);
        const float* ov = o + t * 21;
        float m = -1e30f;
        for (int j = 0; j < 21; j++) m = fmaxf(m, ov[j]);
        float den = 0.f, num = 0.f;
        for (int j = 0; j < 21; j++) { float e = __expf(ov[j] - m); den += e; num += e * wv[j]; }
        soeo[t] = num / den;
    }
    __syncthreads();

    if (t == 0) {
        float stt = anchors[a * 2], enn = anchors[a * 2 + 1];
        out[a * 2]      = fminf(fmaxf(stt + soeo[0], 0.f), al);
        out[a * 2 + 1]  = fminf(fmaxf(enn + soeo[1], 0.f), al);
        out[2 * NA + a] = o[42];
    }
    if (t < 4) out[3 * NA + a * 4 + t] = o[43 + t];
}

// ---------------- launcher ----------------
extern "C" void kernel_launch(void* const* d_in, const int* in_sizes, int n_in,
                              void* d_out, int out_size)
{
    const float* emb   = (const float*)d_in[0];
    const float* tp    = (const float*)d_in[1];
    const float* pred  = (const float*)d_in[2];
    const float* al_p  = (const float*)d_in[3];
    const float* anc   = (const float*)d_in[4];
    const float* kern  = (const float*)d_in[5];
    const float* fWih  = (const float*)d_in[6];
    const float* fWhh  = (const float*)d_in[7];
    const float* fbih  = (const float*)d_in[8];
    const float* fbhh  = (const float*)d_in[9];
    const float* aWih  = (const float*)d_in[10];
    const float* aWhh  = (const float*)d_in[11];
    const float* abih  = (const float*)d_in[12];
    const float* abhh  = (const float*)d_in[13];
    const float* sw    = (const float*)d_in[14];
    const float* ew    = (const float*)d_in[15];
    const float* W1    = (const float*)d_in[16];
    const float* b1    = (const float*)d_in[17];
    const float* W2    = (const float*)d_in[18];
    const float* b2    = (const float*)d_in[19];
    const float* W3    = (const float*)d_in[20];
    const float* b3    = (const float*)d_in[21];
    float* outp = (float*)d_out;

    k_pre<<<(N_NODES * DIM + 255) / 256, 256>>>(emb, tp, pred, al_p, kern);
    k_tr<<<dim3(48, 6), dim3(32, 8)>>>(fWih, fWhh);
    k_gi<<<dim3(32, 7), 384>>>(fbih, anc);
    k_gru<<<NA * 2, 768>>>(anc, fbhh, aWih, aWhh, abih, abhh);
    k_head<<<NA, 256>>>(anc, al_p, W1, b1, W2, b2, W3, b3, sw, ew, outp);
}

// round 7
// speedup vs baseline: 1.4328x; 1.1322x over previous
#include <cuda_runtime.h>
#include <math.h>

#define N_NODES 512
#define DIM 128
#define NA 192          // total anchors
#define G3 384          // 3*DIM
typedef unsigned long long ULL;

// ---------------- scratch (no allocations allowed) ----------------
__device__ float g_x[N_NODES * DIM];
__device__ float g_abn[N_NODES];
__device__ float g_tpos[N_NODES];
__device__ float g_Gi[6 * N_NODES * G3];
__device__ float g_hout[NA * 2 * DIM];
__device__ float g_abnout[NA * 2];
__device__ float g_WihT[6 * DIM * G3];   // [sd][k][row]
__device__ float g_WhhT[6 * DIM * G3];   // [sd][k][row]
__device__ int   g_pairs[96][2];         // [scale*32+pair][2], len-matched within scale
__device__ int   g_order[96];            // pair schedule, len desc

__device__ __forceinline__ float sigf(float x) { return 1.f / (1.f + __expf(-x)); }
__device__ __forceinline__ float tanhfast(float x) { return 2.f / (1.f + __expf(-2.f * x)) - 1.f; }

// ---------------- kernel 1: preprocess ----------------
__global__ void k_pre(const float* __restrict__ emb, const float* __restrict__ tp,
                      const float* __restrict__ pred, const float* __restrict__ al_p,
                      const float* __restrict__ kern)
{
    int tid = blockIdx.x * blockDim.x + threadIdx.x;
    if (tid < N_NODES * DIM) {
        int n = tid >> 7, d = tid & 127;
        float freq = (10.f / 127.f) * (float)d;
        g_x[tid] = emb[tid] + 0.05f * sinf(tp[n] * freq);
    }
    if (tid < N_NODES) {
        int n = tid;
        float kv[5];
        #pragma unroll
        for (int k = 0; k < 5; k++) kv[k] = kern[k];
        float sv[5];
        #pragma unroll
        for (int c = 0; c < 5; c++) {
            float acc = 0.f;
            #pragma unroll
            for (int k = 0; k < 5; k++) {
                int nn = n + k - 2;
                if (nn >= 0 && nn < N_NODES) acc += kv[k] * pred[nn * 5 + c];
            }
            sv[c] = acc;
        }
        float m = sv[0];
        #pragma unroll
        for (int c = 1; c < 5; c++) m = fmaxf(m, sv[c]);
        float den = 0.f;
        #pragma unroll
        for (int c = 0; c < 5; c++) den += __expf(sv[c] - m);
        g_abn[n] = __expf(sv[0] - m) / den;
        g_tpos[n] = tp[n] * al_p[0];
    }
}

// ---------------- kernel 2: tiled transpose of GRU weights ----------------
__global__ void k_tr(const float* __restrict__ Wih, const float* __restrict__ Whh)
{
    __shared__ float s1[32][33];
    __shared__ float s2[32][33];
    int sd = blockIdx.y;
    int ktile = blockIdx.x & 3, rtile = blockIdx.x >> 2;
    int x = threadIdx.x, y = threadIdx.y;
    size_t base = (size_t)sd * G3 * DIM;
    #pragma unroll
    for (int j = 0; j < 4; j++) {
        int r = rtile * 32 + y * 4 + j;
        s1[y * 4 + j][x] = Wih[base + (size_t)r * DIM + ktile * 32 + x];
        s2[y * 4 + j][x] = Whh[base + (size_t)r * DIM + ktile * 32 + x];
    }
    __syncthreads();
    size_t obase = (size_t)sd * DIM * G3;
    #pragma unroll
    for (int j = 0; j < 4; j++) {
        int k = ktile * 32 + y * 4 + j;
        g_WihT[obase + (size_t)k * G3 + rtile * 32 + x] = s1[x][y * 4 + j];
        g_WhhT[obase + (size_t)k * G3 + rtile * 32 + x] = s2[x][y * 4 + j];
    }
}

// ---------------- kernel 3: Gi precompute + pair ranking (y==6) ----------------
__global__ __launch_bounds__(384) void k_gi(const float* __restrict__ bih,
                                            const float* __restrict__ anchors)
{
    int t = threadIdx.x;
    if (blockIdx.y == 6) {
        if (blockIdx.x != 0) return;
        __shared__ float tps[N_NODES];
        __shared__ int lens[NA];
        __shared__ int plen[96];
        for (int i = t; i < N_NODES; i += 384) tps[i] = g_tpos[i];
        __syncthreads();
        if (t < NA) {
            float stt = anchors[2 * t], enn = anchors[2 * t + 1];
            int c = 0;
            for (int n = 0; n < N_NODES; n++)
                c += (tps[n] >= stt && tps[n] <= enn) ? 1 : 0;
            lens[t] = c;
        }
        __syncthreads();
        if (t < NA) {
            int s = t >> 6, base = s * 64;
            int L = lens[t];
            int r = 0;
            for (int j = 0; j < 64; j++) {
                int Lj = lens[base + j];
                if (Lj > L || (Lj == L && base + j < t)) r++;
            }
            g_pairs[s * 32 + (r >> 1)][r & 1] = t;
            if ((r & 1) == 0) plen[s * 32 + (r >> 1)] = L;   // slot0 = longer of pair
        }
        __syncthreads();
        if (t < 96) {
            int L = plen[t];
            int g = 0;
            for (int j = 0; j < 96; j++) {
                int Lj = plen[j];
                if (Lj > L || (Lj == L && j < t)) g++;
            }
            g_order[g] = t;
        }
        return;
    }

    int sd = blockIdx.y, chunk = blockIdx.x;
    __shared__ __align__(16) float sx[16 * DIM];
    const float4* src = (const float4*)(g_x + (size_t)chunk * 16 * DIM);
    for (int i = t; i < 16 * DIM / 4; i += 384) ((float4*)sx)[i] = src[i];

    const float* wt = g_WihT + (size_t)sd * DIM * G3 + t;
    ULL w[64];
    #pragma unroll
    for (int k = 0; k < 64; k++) {
        float w0 = wt[(size_t)(2 * k) * G3];
        float w1 = wt[(size_t)(2 * k + 1) * G3];
        asm("mov.b64 %0,{%1,%2};" : "=l"(w[k]) : "f"(w0), "f"(w1));
    }
    float b = bih[sd * G3 + t];
    unsigned xb;
    asm("{.reg .u64 t0; cvta.to.shared.u64 t0,%1; cvt.u32.u64 %0,t0;}" : "=r"(xb) : "l"((float*)sx));
    __syncthreads();

    float* outp = g_Gi + ((size_t)sd * N_NODES + chunk * 16) * G3 + t;
    float zf = 0.f;
    for (int n = 0; n < 16; n++) {
        ULL acA, acB;
        asm("mov.b64 %0,{%1,%2};" : "=l"(acA) : "f"(b), "f"(zf));
        asm("mov.b64 %0,{%1,%2};" : "=l"(acB) : "f"(zf), "f"(zf));
        unsigned base = xb + n * 512;
        #pragma unroll
        for (int i = 0; i < 16; i++) {
            ULL p0, p1, p2, p3;
            asm volatile("ld.shared.v2.b64 {%0,%1},[%2];" : "=l"(p0), "=l"(p1) : "r"(base + i * 32));
            asm volatile("ld.shared.v2.b64 {%0,%1},[%2];" : "=l"(p2), "=l"(p3) : "r"(base + i * 32 + 16));
            asm("fma.rn.f32x2 %0,%1,%2,%0;" : "+l"(acA) : "l"(w[4 * i])     , "l"(p0));
            asm("fma.rn.f32x2 %0,%1,%2,%0;" : "+l"(acB) : "l"(w[4 * i + 1]) , "l"(p1));
            asm("fma.rn.f32x2 %0,%1,%2,%0;" : "+l"(acA) : "l"(w[4 * i + 2]) , "l"(p2));
            asm("fma.rn.f32x2 %0,%1,%2,%0;" : "+l"(acB) : "l"(w[4 * i + 3]) , "l"(p3));
        }
        float a0, a1, b0, b1;
        asm("mov.b64 {%0,%1},%2;" : "=f"(a0), "=f"(a1) : "l"(acA));
        asm("mov.b64 {%0,%1},%2;" : "=f"(b0), "=f"(b1) : "l"(acB));
        outp[(size_t)n * G3] = (a0 + a1) + (b0 + b1);
    }
}

// ---------------- kernel 4: GRU, 2 len-matched anchors/block, Gi prefetch-ahead ----------------
__global__ __launch_bounds__(384, 1) void k_gru(const float* __restrict__ anchors,
                                                const float* __restrict__ bhh,
                                                const float* __restrict__ aWih,
                                                const float* __restrict__ aWhh,
                                                const float* __restrict__ abih,
                                                const float* __restrict__ abhh)
{
    int t = threadIdx.x;
    __shared__ int sh_task[4];
    __shared__ __align__(16) float hA[DIM];
    __shared__ __align__(16) float hB[DIM];
    __shared__ float ghA[G3];
    __shared__ float ghB[G3];
    __shared__ unsigned short idxA[N_NODES];
    __shared__ unsigned short idxB[N_NODES];
    __shared__ int sh_len[2];
    __shared__ float sh_abh[2];
    __shared__ float aw[12];

    if (t == 0) {
        int pr = g_order[blockIdx.x >> 1];
        sh_task[0] = g_pairs[pr][0];
        sh_task[1] = g_pairs[pr][1];
        sh_task[2] = pr >> 5;              // scale
        sh_task[3] = blockIdx.x & 1;       // dir
    }
    __syncthreads();
    int aA = sh_task[0], aB = sh_task[1], s = sh_task[2], dir = sh_task[3];
    int sd = s * 2 + dir;

    int wid = t >> 5, lane = t & 31;
    if (wid < 2) {                          // warp0->A, warp1->B: compact + reverse if bwd
        int aa = wid ? aB : aA;
        float stt = anchors[2 * aa], enn = anchors[2 * aa + 1];
        unsigned short* ix = wid ? idxB : idxA;
        int off = 0;
        for (int base = 0; base < N_NODES; base += 32) {
            int n = base + lane;
            float tp = g_tpos[n];
            bool m = (tp >= stt) && (tp <= enn);
            unsigned bal = __ballot_sync(0xffffffffu, m);
            if (m) ix[off + __popc(bal & ((1u << lane) - 1u))] = (unsigned short)n;
            off += __popc(bal);
        }
        if (dir) {
            for (int i = lane; i < (off >> 1); i += 32) {
                unsigned short tmp = ix[i];
                ix[i] = ix[off - 1 - i];
                ix[off - 1 - i] = tmp;
            }
        }
        if (lane == 0) { sh_len[wid] = off; sh_abh[wid] = 0.f; }
    }
    if (t < DIM) { hA[t] = 0.f; hB[t] = 0.f; }
    {
        int base = sd * 3;
        if (t >= 64 && t < 67)  aw[t - 64]      = aWih[base + t - 64];
        if (t >= 67 && t < 70)  aw[3 + t - 67]  = aWhh[base + t - 67];
        if (t >= 70 && t < 73)  aw[6 + t - 70]  = abih[base + t - 70];
        if (t >= 73 && t < 76)  aw[9 + t - 73]  = abhh[base + t - 73];
    }

    // Whh row t -> registers (64 f32x2-packed k-pairs, coalesced from WhhT)
    const float* wt = g_WhhT + (size_t)sd * DIM * G3 + t;
    ULL w[64];
    #pragma unroll
    for (int k = 0; k < 64; k++) {
        float w0 = wt[(size_t)(2 * k) * G3];
        float w1 = wt[(size_t)(2 * k + 1) * G3];
        asm("mov.b64 %0,{%1,%2};" : "=l"(w[k]) : "f"(w0), "f"(w1));
    }
    float bh = bhh[sd * G3 + t];
    float zf = 0.f;

    unsigned hbA, hbB;
    asm("{.reg .u64 t0; cvta.to.shared.u64 t0,%1; cvt.u32.u64 %0,t0;}" : "=r"(hbA) : "l"((float*)hA));
    asm("{.reg .u64 t0; cvta.to.shared.u64 t0,%1; cvt.u32.u64 %0,t0;}" : "=r"(hbB) : "l"((float*)hB));
    __syncthreads();

    int lenA = sh_len[0], lenB = sh_len[1];
    int L = lenA > lenB ? lenA : lenB;
    const float* Gi = g_Gi + (size_t)sd * N_NODES * G3;

    bool roleA = (t < 128);
    bool roleB = (t >= 128 && t < 256);
    int tt = t & 127;
    int mylen = roleA ? lenA : (roleB ? lenB : 0);
    const unsigned short* myidx = roleA ? idxA : idxB;

    // preload gate inputs for step 0
    float c0 = 0.f, c1 = 0.f, c2 = 0.f;
    if ((roleA || roleB) && mylen > 0) {
        const float* gp = Gi + (size_t)myidx[0] * G3;
        c0 = gp[tt]; c1 = gp[DIM + tt]; c2 = gp[2 * DIM + tt];
    }
    float abc = 0.f;
    if (t == 256 && lenA > 0) abc = g_abn[idxA[0]];
    if (t == 257 && lenB > 0) abc = g_abn[idxB[0]];

    for (int step = 0; step < L; step++) {
        // prefetch next step's gate inputs (full-iteration latency cover)
        float n0 = 0.f, n1 = 0.f, n2 = 0.f, abn_next = 0.f;
        int sn = step + 1;
        if ((roleA || roleB) && sn < mylen) {
            const float* gp = Gi + (size_t)myidx[sn] * G3;
            n0 = gp[tt]; n1 = gp[DIM + tt]; n2 = gp[2 * DIM + tt];
        }
        if (t == 256 && sn < lenA) abn_next = g_abn[idxA[sn]];
        if (t == 257 && sn < lenB) abn_next = g_abn[idxB[sn]];

        // dot: gh[t] = Whh_row_t . h + bh, for both anchors (shared weights)
        ULL accA, accB;
        asm("mov.b64 %0,{%1,%2};" : "=l"(accA) : "f"(bh), "f"(zf));
        asm("mov.b64 %0,{%1,%2};" : "=l"(accB) : "f"(bh), "f"(zf));
        #pragma unroll
        for (int i = 0; i < 32; i++) {
            ULL a0, a1, b0, b1;
            asm volatile("ld.shared.v2.b64 {%0,%1},[%2];" : "=l"(a0), "=l"(a1) : "r"(hbA + i * 16));
            asm volatile("ld.shared.v2.b64 {%0,%1},[%2];" : "=l"(b0), "=l"(b1) : "r"(hbB + i * 16));
            asm("fma.rn.f32x2 %0,%1,%2,%0;" : "+l"(accA) : "l"(w[2 * i])     , "l"(a0));
            asm("fma.rn.f32x2 %0,%1,%2,%0;" : "+l"(accB) : "l"(w[2 * i])     , "l"(b0));
            asm("fma.rn.f32x2 %0,%1,%2,%0;" : "+l"(accA) : "l"(w[2 * i + 1]) , "l"(a1));
            asm("fma.rn.f32x2 %0,%1,%2,%0;" : "+l"(accB) : "l"(w[2 * i + 1]) , "l"(b1));
        }
        float pa0, pa1, pb0, pb1;
        asm("mov.b64 {%0,%1},%2;" : "=f"(pa0), "=f"(pa1) : "l"(accA));
        asm("mov.b64 {%0,%1},%2;" : "=f"(pb0), "=f"(pb1) : "l"(accB));
        ghA[t] = pa0 + pa1;
        ghB[t] = pb0 + pb1;
        __syncthreads();

        bool actA = step < lenA, actB = step < lenB;
        if (roleA) {
            if (actA) {
                float r  = sigf(c0 + ghA[tt]);
                float z  = sigf(c1 + ghA[DIM + tt]);
                float nn = tanhfast(c2 + r * ghA[2 * DIM + tt]);
                hA[tt] = (1.f - z) * nn + z * hA[tt];
            }
        } else if (roleB) {
            if (actB) {
                float r  = sigf(c0 + ghB[tt]);
                float z  = sigf(c1 + ghB[DIM + tt]);
                float nn = tanhfast(c2 + r * ghB[2 * DIM + tt]);
                hB[tt] = (1.f - z) * nn + z * hB[tt];
            }
        } else if (t == 256) {
            if (actA) {
                float h = sh_abh[0];
                float r  = sigf(aw[0] * abc + aw[6] + aw[3] * h + aw[9]);
                float z  = sigf(aw[1] * abc + aw[7] + aw[4] * h + aw[10]);
                float nn = tanhfast(aw[2] * abc + aw[8] + r * (aw[5] * h + aw[11]));
                sh_abh[0] = (1.f - z) * nn + z * h;
            }
        } else if (t == 257) {
            if (actB) {
                float h = sh_abh[1];
                float r  = sigf(aw[0] * abc + aw[6] + aw[3] * h + aw[9]);
                float z  = sigf(aw[1] * abc + aw[7] + aw[4] * h + aw[10]);
                float nn = tanhfast(aw[2] * abc + aw[8] + r * (aw[5] * h + aw[11]));
                sh_abh[1] = (1.f - z) * nn + z * h;
            }
        }
        c0 = n0; c1 = n1; c2 = n2; abc = abn_next;
        __syncthreads();
    }

    if (roleA)      g_hout[((size_t)aA * 2 + dir) * DIM + tt] = hA[tt];
    else if (roleB) g_hout[((size_t)aB * 2 + dir) * DIM + tt] = hB[tt];
    else if (t == 256) g_abnout[aA * 2 + dir] = sh_abh[0];
    else if (t == 257) g_abnout[aB * 2 + dir] = sh_abh[1];
}

// ---------------- kernel 5: per-anchor MLP head, 8-way ILP ----------------
__global__ __launch_bounds__(256) void k_head(const float* __restrict__ anchors,
                                              const float* __restrict__ al_p,
                                              const float* __restrict__ W1, const float* __restrict__ b1,
                                              const float* __restrict__ W2, const float* __restrict__ b2,
                                              const float* __restrict__ W3, const float* __restrict__ b3,
                                              const float* __restrict__ start_w,
                                              const float* __restrict__ end_w,
                                              float* __restrict__ out)
{
    int a = blockIdx.x;
    int s = a >> 6;
    int t = threadIdx.x;
    const int FIN = 2 * DIM + 3;   // 259
    const int FOUT = 47;

    __shared__ float sf[FIN + 1];
    __shared__ float h1[256];
    __shared__ float h2[256];
    __shared__ float o[FOUT];
    __shared__ float soeo[2];

    float al = al_p[0];
    if (t < DIM) {
        sf[t]       = g_hout[((size_t)a * 2 + 0) * DIM + t];
        sf[DIM + t] = g_hout[((size_t)a * 2 + 1) * DIM + t];
    }
    if (t == 0) {
        sf[256] = 0.5f * (g_abnout[a * 2] + g_abnout[a * 2 + 1]);
        float stt = anchors[a * 2], enn = anchors[a * 2 + 1];
        sf[257] = (stt + enn) * 0.5f / al;
        sf[258] = (enn - stt) / al;
    }
    __syncthreads();

    {
        const float* W = W1 + (size_t)s * FIN * 256 + t;
        float acc[8];
        #pragma unroll
        for (int j = 0; j < 8; j++) acc[j] = 0.f;
        for (int i = 0; i < 256; i += 8) {
            #pragma unroll
            for (int j = 0; j < 8; j++) acc[j] += W[(size_t)(i + j) * 256] * sf[i + j];
        }
        acc[0] += W[(size_t)256 * 256] * sf[256];
        acc[1] += W[(size_t)257 * 256] * sf[257];
        acc[2] += W[(size_t)258 * 256] * sf[258];
        float r = (((acc[0] + acc[1]) + (acc[2] + acc[3])) + ((acc[4] + acc[5]) + (acc[6] + acc[7])))
                  + b1[s * 256 + t];
        h1[t] = fmaxf(r, 0.f);
    }
    __syncthreads();

    {
        const float* W = W2 + (size_t)s * 256 * 256 + t;
        float acc[8];
        #pragma unroll
        for (int j = 0; j < 8; j++) acc[j] = 0.f;
        for (int i = 0; i < 256; i += 8) {
            #pragma unroll
            for (int j = 0; j < 8; j++) acc[j] += W[(size_t)(i + j) * 256] * h1[i + j];
        }
        float r = (((acc[0] + acc[1]) + (acc[2] + acc[3])) + ((acc[4] + acc[5]) + (acc[6] + acc[7])))
                  + b2[s * 256 + t];
        h2[t] = fmaxf(r, 0.f);
    }
    __syncthreads();

    if (t < FOUT) {
        const float* W = W3 + (size_t)s * 256 * FOUT + t;
        float acc[8];
        #pragma unroll
        for (int j = 0; j < 8; j++) acc[j] = 0.f;
        for (int i = 0; i < 256; i += 8) {
            #pragma unroll
            for (int j = 0; j < 8; j++) acc[j] += W[(size_t)(i + j) * FOUT] * h2[i + j];
        }
        o[t] = (((acc[0] + acc[1]) + (acc[2] + acc[3])) + ((acc[4] + acc[5]) + (acc[6] + acc[7])))
               + b3[s * FOUT + t];
    }
    __syncthreads();

    if (t < 2) {
        const float* wv = (t == 0) ? (start_w + s * 21) : (end_w + s * 21);
        const float* ov = o + t * 21;
        float m = -1e30f;
        for (int j = 0; j < 21; j++) m = fmaxf(m, ov[j]);
        float den = 0.f, num = 0.f;
        for (int j = 0; j < 21; j++) { float e = __expf(ov[j] - m); den += e; num += e * wv[j]; }
        soeo[t] = num / den;
    }
    __syncthreads();

    if (t == 0) {
        float stt = anchors[a * 2], enn = anchors[a * 2 + 1];
        out[a * 2]      = fminf(fmaxf(stt + soeo[0], 0.f), al);
        out[a * 2 + 1]  = fminf(fmaxf(enn + soeo[1], 0.f), al);
        out[2 * NA + a] = o[42];
    }
    if (t < 4) out[3 * NA + a * 4 + t] = o[43 + t];
}

// ---------------- launcher ----------------
extern "C" void kernel_launch(void* const* d_in, const int* in_sizes, int n_in,
                              void* d_out, int out_size)
{
    const float* emb   = (const float*)d_in[0];
    const float* tp    = (const float*)d_in[1];
    const float* pred  = (const float*)d_in[2];
    const float* al_p  = (const float*)d_in[3];
    const float* anc   = (const float*)d_in[4];
    const float* kern  = (const float*)d_in[5];
    const float* fWih  = (const float*)d_in[6];
    const float* fWhh  = (const float*)d_in[7];
    const float* fbih  = (const float*)d_in[8];
    const float* fbhh  = (const float*)d_in[9];
    const float* aWih  = (const float*)d_in[10];
    const float* aWhh  = (const float*)d_in[11];
    const float* abih  = (const float*)d_in[12];
    const float* abhh  = (const float*)d_in[13];
    const float* sw    = (const float*)d_in[14];
    const float* ew    = (const float*)d_in[15];
    const float* W1    = (const float*)d_in[16];
    const float* b1    = (const float*)d_in[17];
    const float* W2    = (const float*)d_in[18];
    const float* b2    = (const float*)d_in[19];
    const float* W3    = (const float*)d_in[20];
    const float* b3    = (const float*)d_in[21];
    float* outp = (float*)d_out;

    k_pre<<<(N_NODES * DIM + 255) / 256, 256>>>(emb, tp, pred, al_p, kern);
    k_tr<<<dim3(48, 6), dim3(32, 8)>>>(fWih, fWhh);
    k_gi<<<dim3(32, 7), 384>>>(fbih, anc);
    k_gru<<<NA, 384>>>(anc, fbhh, aWih, aWhh, abih, abhh);
    k_head<<<NA, 256>>>(anc, al_p, W1, b1, W2, b2, W3, b3, sw, ew, outp);
}

// round 8
// speedup vs baseline: 1.4630x; 1.0211x over previous
#include <cuda_runtime.h>
#include <math.h>

#define N_NODES 512
#define DIM 128
#define NA 192          // total anchors
#define G3 384          // 3*DIM
typedef unsigned long long ULL;

// ---------------- scratch (no allocations allowed) ----------------
__device__ float g_x[N_NODES * DIM];
__device__ float g_abn[N_NODES];
__device__ float g_tpos[N_NODES];
__device__ float g_Gi[6 * N_NODES * G3];
__device__ float g_hout[NA * 2 * DIM];
__device__ float g_abnout[NA * 2];
__device__ float g_WihT[6 * DIM * G3];   // [sd][k][row]
__device__ float g_WhhT[6 * DIM * G3];   // [sd][k][row]
__device__ int   g_pairs[96][2];         // [scale*32+pair][2], len-matched within scale
__device__ int   g_order[96];            // pair schedule, len desc

__device__ __forceinline__ float sigf(float x) { return 1.f / (1.f + __expf(-x)); }
__device__ __forceinline__ float tanhfast(float x) { return 2.f / (1.f + __expf(-2.f * x)) - 1.f; }

// ---------------- kernel 1 (fused): preprocess + weight transpose ----------------
// blocks [0,256): k_pre work. blocks [256,544): tiled transpose.
__global__ void k_pre_tr(const float* __restrict__ emb, const float* __restrict__ tp,
                         const float* __restrict__ pred, const float* __restrict__ al_p,
                         const float* __restrict__ kern,
                         const float* __restrict__ Wih, const float* __restrict__ Whh)
{
    int b = blockIdx.x;
    int t = threadIdx.x;
    if (b < 256) {
        int tid = b * 256 + t;
        if (tid < N_NODES * DIM) {
            int n = tid >> 7, d = tid & 127;
            float freq = (10.f / 127.f) * (float)d;
            g_x[tid] = emb[tid] + 0.05f * sinf(tp[n] * freq);
        }
        if (tid < N_NODES) {
            int n = tid;
            float kv[5];
            #pragma unroll
            for (int k = 0; k < 5; k++) kv[k] = kern[k];
            float sv[5];
            #pragma unroll
            for (int c = 0; c < 5; c++) {
                float acc = 0.f;
                #pragma unroll
                for (int k = 0; k < 5; k++) {
                    int nn = n + k - 2;
                    if (nn >= 0 && nn < N_NODES) acc += kv[k] * pred[nn * 5 + c];
                }
                sv[c] = acc;
            }
            float m = sv[0];
            #pragma unroll
            for (int c = 1; c < 5; c++) m = fmaxf(m, sv[c]);
            float den = 0.f;
            #pragma unroll
            for (int c = 0; c < 5; c++) den += __expf(sv[c] - m);
            g_abn[n] = __expf(sv[0] - m) / den;
            g_tpos[n] = tp[n] * al_p[0];
        }
        return;
    }
    // transpose part
    __shared__ float s1[32][33];
    __shared__ float s2[32][33];
    int bb = b - 256;
    int sd = bb / 48, bx = bb % 48;
    int ktile = bx & 3, rtile = bx >> 2;
    int x = t & 31, y = t >> 5;
    size_t base = (size_t)sd * G3 * DIM;
    #pragma unroll
    for (int j = 0; j < 4; j++) {
        int r = rtile * 32 + y * 4 + j;
        s1[y * 4 + j][x] = Wih[base + (size_t)r * DIM + ktile * 32 + x];
        s2[y * 4 + j][x] = Whh[base + (size_t)r * DIM + ktile * 32 + x];
    }
    __syncthreads();
    size_t obase = (size_t)sd * DIM * G3;
    #pragma unroll
    for (int j = 0; j < 4; j++) {
        int k = ktile * 32 + y * 4 + j;
        g_WihT[obase + (size_t)k * G3 + rtile * 32 + x] = s1[x][y * 4 + j];
        g_WhhT[obase + (size_t)k * G3 + rtile * 32 + x] = s2[x][y * 4 + j];
    }
}

// ---------------- kernel 2: Gi precompute + pair ranking (y==6) ----------------
__global__ __launch_bounds__(384) void k_gi(const float* __restrict__ bih,
                                            const float* __restrict__ anchors)
{
    int t = threadIdx.x;
    if (blockIdx.y == 6) {
        if (blockIdx.x != 0) return;
        __shared__ float tps[N_NODES];
        __shared__ int lens[NA];
        __shared__ int plen[96];
        for (int i = t; i < N_NODES; i += 384) tps[i] = g_tpos[i];
        __syncthreads();
        if (t < NA) {
            float stt = anchors[2 * t], enn = anchors[2 * t + 1];
            int c = 0;
            for (int n = 0; n < N_NODES; n++)
                c += (tps[n] >= stt && tps[n] <= enn) ? 1 : 0;
            lens[t] = c;
        }
        __syncthreads();
        if (t < NA) {
            int s = t >> 6, base = s * 64;
            int L = lens[t];
            int r = 0;
            for (int j = 0; j < 64; j++) {
                int Lj = lens[base + j];
                if (Lj > L || (Lj == L && base + j < t)) r++;
            }
            g_pairs[s * 32 + (r >> 1)][r & 1] = t;
            if ((r & 1) == 0) plen[s * 32 + (r >> 1)] = L;
        }
        __syncthreads();
        if (t < 96) {
            int L = plen[t];
            int g = 0;
            for (int j = 0; j < 96; j++) {
                int Lj = plen[j];
                if (Lj > L || (Lj == L && j < t)) g++;
            }
            g_order[g] = t;
        }
        return;
    }

    int sd = blockIdx.y, chunk = blockIdx.x;
    __shared__ __align__(16) float sx[16 * DIM];
    const float4* src = (const float4*)(g_x + (size_t)chunk * 16 * DIM);
    for (int i = t; i < 16 * DIM / 4; i += 384) ((float4*)sx)[i] = src[i];

    const float* wt = g_WihT + (size_t)sd * DIM * G3 + t;
    ULL w[64];
    #pragma unroll
    for (int k = 0; k < 64; k++) {
        float w0 = wt[(size_t)(2 * k) * G3];
        float w1 = wt[(size_t)(2 * k + 1) * G3];
        asm("mov.b64 %0,{%1,%2};" : "=l"(w[k]) : "f"(w0), "f"(w1));
    }
    float b = bih[sd * G3 + t];
    unsigned xb;
    asm("{.reg .u64 t0; cvta.to.shared.u64 t0,%1; cvt.u32.u64 %0,t0;}" : "=r"(xb) : "l"((float*)sx));
    __syncthreads();

    float* outp = g_Gi + ((size_t)sd * N_NODES + chunk * 16) * G3 + t;
    #pragma unroll 2
    for (int n = 0; n < 16; n++) {
        ULL acA = 0ull, acB = 0ull;
        unsigned base = xb + n * 512;
        #pragma unroll
        for (int i = 0; i < 16; i++) {
            ULL p0, p1, p2, p3;
            asm volatile("ld.shared.v2.b64 {%0,%1},[%2];" : "=l"(p0), "=l"(p1) : "r"(base + i * 32));
            asm volatile("ld.shared.v2.b64 {%0,%1},[%2];" : "=l"(p2), "=l"(p3) : "r"(base + i * 32 + 16));
            asm("fma.rn.f32x2 %0,%1,%2,%0;" : "+l"(acA) : "l"(w[4 * i])     , "l"(p0));
            asm("fma.rn.f32x2 %0,%1,%2,%0;" : "+l"(acB) : "l"(w[4 * i + 1]) , "l"(p1));
            asm("fma.rn.f32x2 %0,%1,%2,%0;" : "+l"(acA) : "l"(w[4 * i + 2]) , "l"(p2));
            asm("fma.rn.f32x2 %0,%1,%2,%0;" : "+l"(acB) : "l"(w[4 * i + 3]) , "l"(p3));
        }
        float a0, a1, b0, b1;
        asm("mov.b64 {%0,%1},%2;" : "=f"(a0), "=f"(a1) : "l"(acA));
        asm("mov.b64 {%0,%1},%2;" : "=f"(b0), "=f"(b1) : "l"(acB));
        outp[(size_t)n * G3] = ((a0 + a1) + (b0 + b1)) + b;
    }
}

// ---------------- kernel 3: GRU, 2 len-matched anchors/block, 4 acc chains ----------------
__global__ __launch_bounds__(384, 1) void k_gru(const float* __restrict__ anchors,
                                                const float* __restrict__ bhh,
                                                const float* __restrict__ aWih,
                                                const float* __restrict__ aWhh,
                                                const float* __restrict__ abih,
                                                const float* __restrict__ abhh)
{
    int t = threadIdx.x;
    __shared__ int sh_task[4];
    __shared__ __align__(16) float sh_h[2][DIM];     // contiguous: B at +512 bytes
    __shared__ float ghA[G3];
    __shared__ float ghB[G3];
    __shared__ unsigned short idxAB[2][N_NODES];     // contiguous: B at +1024 bytes
    __shared__ int sh_len[2];
    __shared__ float sh_abh[2];
    __shared__ float aw[12];

    if (t == 0) {
        int pr = g_order[blockIdx.x >> 1];
        sh_task[0] = g_pairs[pr][0];
        sh_task[1] = g_pairs[pr][1];
        sh_task[2] = pr >> 5;
        sh_task[3] = blockIdx.x & 1;
    }
    __syncthreads();
    int aA = sh_task[0], aB = sh_task[1], s = sh_task[2], dir = sh_task[3];
    int sd = s * 2 + dir;

    int wid = t >> 5, lane = t & 31;
    if (wid < 2) {
        int aa = wid ? aB : aA;
        float stt = anchors[2 * aa], enn = anchors[2 * aa + 1];
        unsigned short* ix = idxAB[wid];
        int off = 0;
        for (int base = 0; base < N_NODES; base += 32) {
            int n = base + lane;
            float tp = g_tpos[n];
            bool m = (tp >= stt) && (tp <= enn);
            unsigned bal = __ballot_sync(0xffffffffu, m);
            if (m) ix[off + __popc(bal & ((1u << lane) - 1u))] = (unsigned short)n;
            off += __popc(bal);
        }
        if (dir) {
            for (int i = lane; i < (off >> 1); i += 32) {
                unsigned short tmp = ix[i];
                ix[i] = ix[off - 1 - i];
                ix[off - 1 - i] = tmp;
            }
        }
        if (lane == 0) { sh_len[wid] = off; sh_abh[wid] = 0.f; }
    }
    if (t < DIM) { sh_h[0][t] = 0.f; sh_h[1][t] = 0.f; }
    {
        int base = sd * 3;
        if (t >= 64 && t < 67)  aw[t - 64]      = aWih[base + t - 64];
        if (t >= 67 && t < 70)  aw[3 + t - 67]  = aWhh[base + t - 67];
        if (t >= 70 && t < 73)  aw[6 + t - 70]  = abih[base + t - 70];
        if (t >= 73 && t < 76)  aw[9 + t - 73]  = abhh[base + t - 73];
    }

    // Whh row t -> registers (64 f32x2-packed k-pairs, coalesced from WhhT)
    const float* wt = g_WhhT + (size_t)sd * DIM * G3 + t;
    ULL w[64];
    #pragma unroll
    for (int k = 0; k < 64; k++) {
        float w0 = wt[(size_t)(2 * k) * G3];
        float w1 = wt[(size_t)(2 * k + 1) * G3];
        asm("mov.b64 %0,{%1,%2};" : "=l"(w[k]) : "f"(w0), "f"(w1));
    }
    float bh = bhh[sd * G3 + t];

    unsigned hb;
    asm("{.reg .u64 t0; cvta.to.shared.u64 t0,%1; cvt.u32.u64 %0,t0;}" : "=r"(hb) : "l"(&sh_h[0][0]));
    __syncthreads();

    int lenA = sh_len[0], lenB = sh_len[1];
    int L = lenA > lenB ? lenA : lenB;
    const float* Gi = g_Gi + (size_t)sd * N_NODES * G3;

    bool roleA = (t < 128);
    bool roleB = (t >= 128 && t < 256);
    int tt = t & 127;
    int mylen = roleA ? lenA : (roleB ? lenB : 0);
    const unsigned short* myidx = roleA ? idxAB[0] : idxAB[1];

    // preload gate inputs for step 0
    float c0 = 0.f, c1 = 0.f, c2 = 0.f;
    if ((roleA || roleB) && mylen > 0) {
        const float* gp = Gi + (size_t)myidx[0] * G3;
        c0 = gp[tt]; c1 = gp[DIM + tt]; c2 = gp[2 * DIM + tt];
    }
    float abc = 0.f;
    if (t == 256 && lenA > 0) abc = g_abn[idxAB[0][0]];
    if (t == 257 && lenB > 0) abc = g_abn[idxAB[1][0]];

    for (int step = 0; step < L; step++) {
        // prefetch next step's gate inputs (full-iteration latency cover)
        float n0 = 0.f, n1 = 0.f, n2 = 0.f, abn_next = 0.f;
        int sn = step + 1;
        if ((roleA || roleB) && sn < mylen) {
            const float* gp = Gi + (size_t)myidx[sn] * G3;
            n0 = gp[tt]; n1 = gp[DIM + tt]; n2 = gp[2 * DIM + tt];
        }
        if (t == 256 && sn < lenA) abn_next = g_abn[idxAB[0][sn]];
        if (t == 257 && sn < lenB) abn_next = g_abn[idxAB[1][sn]];

        // dot: gh[t] = Whh_row_t . h + bh; 4 acc chains, each touched once per iter (8-cyc gap)
        ULL accA0 = 0ull, accA1 = 0ull, accB0 = 0ull, accB1 = 0ull;
        #pragma unroll
        for (int i = 0; i < 32; i++) {
            ULL a0, a1, b0, b1;
            asm volatile("ld.shared.v2.b64 {%0,%1},[%2];" : "=l"(a0), "=l"(a1) : "r"(hb + i * 16));
            asm volatile("ld.shared.v2.b64 {%0,%1},[%2];" : "=l"(b0), "=l"(b1) : "r"(hb + 512 + i * 16));
            asm("fma.rn.f32x2 %0,%1,%2,%0;" : "+l"(accA0) : "l"(w[2 * i])     , "l"(a0));
            asm("fma.rn.f32x2 %0,%1,%2,%0;" : "+l"(accB0) : "l"(w[2 * i])     , "l"(b0));
            asm("fma.rn.f32x2 %0,%1,%2,%0;" : "+l"(accA1) : "l"(w[2 * i + 1]) , "l"(a1));
            asm("fma.rn.f32x2 %0,%1,%2,%0;" : "+l"(accB1) : "l"(w[2 * i + 1]) , "l"(b1));
        }
        float pa0, pa1, pa2, pa3, pb0, pb1, pb2, pb3;
        asm("mov.b64 {%0,%1},%2;" : "=f"(pa0), "=f"(pa1) : "l"(accA0));
        asm("mov.b64 {%0,%1},%2;" : "=f"(pa2), "=f"(pa3) : "l"(accA1));
        asm("mov.b64 {%0,%1},%2;" : "=f"(pb0), "=f"(pb1) : "l"(accB0));
        asm("mov.b64 {%0,%1},%2;" : "=f"(pb2), "=f"(pb3) : "l"(accB1));
        ghA[t] = ((pa0 + pa1) + (pa2 + pa3)) + bh;
        ghB[t] = ((pb0 + pb1) + (pb2 + pb3)) + bh;
        __syncthreads();

        bool actA = step < lenA, actB = step < lenB;
        if (roleA) {
            if (actA) {
                float r  = sigf(c0 + ghA[tt]);
                float z  = sigf(c1 + ghA[DIM + tt]);
                float nn = tanhfast(c2 + r * ghA[2 * DIM + tt]);
                sh_h[0][tt] = (1.f - z) * nn + z * sh_h[0][tt];
            }
        } else if (roleB) {
            if (actB) {
                float r  = sigf(c0 + ghB[tt]);
                float z  = sigf(c1 + ghB[DIM + tt]);
                float nn = tanhfast(c2 + r * ghB[2 * DIM + tt]);
                sh_h[1][tt] = (1.f - z) * nn + z * sh_h[1][tt];
            }
        } else if (t == 256) {
            if (actA) {
                float h = sh_abh[0];
                float r  = sigf(aw[0] * abc + aw[6] + aw[3] * h + aw[9]);
                float z  = sigf(aw[1] * abc + aw[7] + aw[4] * h + aw[10]);
                float nn = tanhfast(aw[2] * abc + aw[8] + r * (aw[5] * h + aw[11]));
                sh_abh[0] = (1.f - z) * nn + z * h;
            }
        } else if (t == 257) {
            if (actB) {
                float h = sh_abh[1];
                float r  = sigf(aw[0] * abc + aw[6] + aw[3] * h + aw[9]);
                float z  = sigf(aw[1] * abc + aw[7] + aw[4] * h + aw[10]);
                float nn = tanhfast(aw[2] * abc + aw[8] + r * (aw[5] * h + aw[11]));
                sh_abh[1] = (1.f - z) * nn + z * h;
            }
        }
        c0 = n0; c1 = n1; c2 = n2; abc = abn_next;
        __syncthreads();
    }

    if (roleA)      g_hout[((size_t)aA * 2 + dir) * DIM + tt] = sh_h[0][tt];
    else if (roleB) g_hout[((size_t)aB * 2 + dir) * DIM + tt] = sh_h[1][tt];
    else if (t == 256) g_abnout[aA * 2 + dir] = sh_abh[0];
    else if (t == 257) g_abnout[aB * 2 + dir] = sh_abh[1];
}

// ---------------- kernel 4: MLP head, 2 anchors (same scale) per block ----------------
__global__ __launch_bounds__(256) void k_head(const float* __restrict__ anchors,
                                              const float* __restrict__ al_p,
                                              const float* __restrict__ W1, const float* __restrict__ b1,
                                              const float* __restrict__ W2, const float* __restrict__ b2,
                                              const float* __restrict__ W3, const float* __restrict__ b3,
                                              const float* __restrict__ start_w,
                                              const float* __restrict__ end_w,
                                              float* __restrict__ out)
{
    int blk = blockIdx.x;            // 0..95
    int s = blk >> 5, j = blk & 31;
    int aA = s * 64 + j, aB = aA + 32;
    int t = threadIdx.x;
    const int FIN = 2 * DIM + 3;     // 259
    const int FOUT = 47;

    __shared__ float sfA[FIN + 1], sfB[FIN + 1];
    __shared__ float h1A[256], h1B[256];
    __shared__ float h2A[256], h2B[256];
    __shared__ float oA[FOUT + 1], oB[FOUT + 1];
    __shared__ float soeo[4];

    float al = al_p[0];
    if (t < DIM) {
        sfA[t]       = g_hout[((size_t)aA * 2 + 0) * DIM + t];
        sfA[DIM + t] = g_hout[((size_t)aA * 2 + 1) * DIM + t];
        sfB[t]       = g_hout[((size_t)aB * 2 + 0) * DIM + t];
        sfB[DIM + t] = g_hout[((size_t)aB * 2 + 1) * DIM + t];
    }
    if (t == 0) {
        sfA[256] = 0.5f * (g_abnout[aA * 2] + g_abnout[aA * 2 + 1]);
        float stt = anchors[aA * 2], enn = anchors[aA * 2 + 1];
        sfA[257] = (stt + enn) * 0.5f / al;
        sfA[258] = (enn - stt) / al;
    }
    if (t == 1) {
        sfB[256] = 0.5f * (g_abnout[aB * 2] + g_abnout[aB * 2 + 1]);
        float stt = anchors[aB * 2], enn = anchors[aB * 2 + 1];
        sfB[257] = (stt + enn) * 0.5f / al;
        sfB[258] = (enn - stt) / al;
    }
    __syncthreads();

    {
        const float* W = W1 + (size_t)s * FIN * 256 + t;
        float accA[8], accB[8];
        #pragma unroll
        for (int q = 0; q < 8; q++) { accA[q] = 0.f; accB[q] = 0.f; }
        for (int i = 0; i < 256; i += 8) {
            #pragma unroll
            for (int q = 0; q < 8; q++) {
                float wv = W[(size_t)(i + q) * 256];
                accA[q] += wv * sfA[i + q];
                accB[q] += wv * sfB[i + q];
            }
        }
        #pragma unroll
        for (int q = 0; q < 3; q++) {
            float wv = W[(size_t)(256 + q) * 256];
            accA[q] += wv * sfA[256 + q];
            accB[q] += wv * sfB[256 + q];
        }
        float rA = (((accA[0] + accA[1]) + (accA[2] + accA[3])) + ((accA[4] + accA[5]) + (accA[6] + accA[7])))
                   + b1[s * 256 + t];
        float rB = (((accB[0] + accB[1]) + (accB[2] + accB[3])) + ((accB[4] + accB[5]) + (accB[6] + accB[7])))
                   + b1[s * 256 + t];
        h1A[t] = fmaxf(rA, 0.f);
        h1B[t] = fmaxf(rB, 0.f);
    }
    __syncthreads();

    {
        const float* W = W2 + (size_t)s * 256 * 256 + t;
        float accA[8], accB[8];
        #pragma unroll
        for (int q = 0; q < 8; q++) { accA[q] = 0.f; accB[q] = 0.f; }
        for (int i = 0; i < 256; i += 8) {
            #pragma unroll
            for (int q = 0; q < 8; q++) {
                float wv = W[(size_t)(i + q) * 256];
                accA[q] += wv * h1A[i + q];
                accB[q] += wv * h1B[i + q];
            }
        }
        float rA = (((accA[0] + accA[1]) + (accA[2] + accA[3])) + ((accA[4] + accA[5]) + (accA[6] + accA[7])))
                   + b2[s * 256 + t];
        float rB = (((accB[0] + accB[1]) + (accB[2] + accB[3])) + ((accB[4] + accB[5]) + (accB[6] + accB[7])))
                   + b2[s * 256 + t];
        h2A[t] = fmaxf(rA, 0.f);
        h2B[t] = fmaxf(rB, 0.f);
    }
    __syncthreads();

    if (t < FOUT) {
        const float* W = W3 + (size_t)s * 256 * FOUT + t;
        float accA[8], accB[8];
        #pragma unroll
        for (int q = 0; q < 8; q++) { accA[q] = 0.f; accB[q] = 0.f; }
        for (int i = 0; i < 256; i += 8) {
            #pragma unroll
            for (int q = 0; q < 8; q++) {
                float wv = W[(size_t)(i + q) * FOUT];
                accA[q] += wv * h2A[i + q];
                accB[q] += wv * h2B[i + q];
            }
        }
        oA[t] = (((accA[0] + accA[1]) + (accA[2] + accA[3])) + ((accA[4] + accA[5]) + (accA[6] + accA[7])))
                + b3[s * FOUT + t];
        oB[t] = (((accB[0] + accB[1]) + (accB[2] + accB[3])) + ((accB[4] + accB[5]) + (accB[6] + accB[7])))
                + b3[s * FOUT + t];
    }
    __syncthreads();

    if (t < 4) {
        const float* ov = (t & 2) ? (oB + (t & 1) * 21) : (oA + (t & 1) * 21);
        const float* wv = (t & 1) ? (end_w + s * 21) : (start_w + s * 21);
        float m = -1e30f;
        for (int q = 0; q < 21; q++) m = fmaxf(m, ov[q]);
        float den = 0.f, num = 0.f;
        for (int q = 0; q < 21; q++) { float e = __expf(ov[q] - m); den += e; num += e * wv[q]; }
        soeo[t] = num / den;
    }
    __syncthreads();

    if (t == 0) {
        float stt = anchors[aA * 2], enn = anchors[aA * 2 + 1];
        out[aA * 2]      = fminf(fmaxf(stt + soeo[0], 0.f), al);
        out[aA * 2 + 1]  = fminf(fmaxf(enn + soeo[1], 0.f), al);
        out[2 * NA + aA] = oA[42];
    }
    if (t == 1) {
        float stt = anchors[aB * 2], enn = anchors[aB * 2 + 1];
        out[aB * 2]      = fminf(fmaxf(stt + soeo[2], 0.f), al);
        out[aB * 2 + 1]  = fminf(fmaxf(enn + soeo[3], 0.f), al);
        out[2 * NA + aB] = oB[42];
    }
    if (t >= 4 && t < 8)  out[3 * NA + aA * 4 + (t - 4)] = oA[43 + (t - 4)];
    if (t >= 8 && t < 12) out[3 * NA + aB * 4 + (t - 8)] = oB[43 + (t - 8)];
}

// ---------------- launcher ----------------
extern "C" void kernel_launch(void* const* d_in, const int* in_sizes, int n_in,
                              void* d_out, int out_size)
{
    const float* emb   = (const float*)d_in[0];
    const float* tp    = (const float*)d_in[1];
    const float* pred  = (const float*)d_in[2];
    const float* al_p  = (const float*)d_in[3];
    const float* anc   = (const float*)d_in[4];
    const float* kern  = (const float*)d_in[5];
    const float* fWih  = (const float*)d_in[6];
    const float* fWhh  = (const float*)d_in[7];
    const float* fbih  = (const float*)d_in[8];
    const float* fbhh  = (const float*)d_in[9];
    const float* aWih  = (const float*)d_in[10];
    const float* aWhh  = (const float*)d_in[11];
    const float* abih  = (const float*)d_in[12];
    const float* abhh  = (const float*)d_in[13];
    const float* sw    = (const float*)d_in[14];
    const float* ew    = (const float*)d_in[15];
    const float* W1    = (const float*)d_in[16];
    const float* b1    = (const float*)d_in[17];
    const float* W2    = (const float*)d_in[18];
    const float* b2    = (const float*)d_in[19];
    const float* W3    = (const float*)d_in[20];
    const float* b3    = (const float*)d_in[21];
    float* outp = (float*)d_out;

    k_pre_tr<<<544, 256>>>(emb, tp, pred, al_p, kern, fWih, fWhh);
    k_gi<<<dim3(32, 7), 384>>>(fbih, anc);
    k_gru<<<NA, 384>>>(anc, fbhh, aWih, aWhh, abih, abhh);
    k_head<<<96, 256>>>(anc, al_p, W1, b1, W2, b2, W3, b3, sw, ew, outp);
}

// round 9
// speedup vs baseline: 1.5790x; 1.0793x over previous
#include <cuda_runtime.h>
#include <math.h>

#define N_NODES 512
#define DIM 128
#define NA 192          // total anchors
#define G3 384          // 3*DIM
typedef unsigned long long ULL;

// ---------------- scratch (no allocations allowed) ----------------
__device__ float g_x[N_NODES * DIM];
__device__ float g_abn[N_NODES];
__device__ float g_tpos[N_NODES];
__device__ float g_Gi[6 * N_NODES * G3];
__device__ float g_hout[NA * 2 * DIM];
__device__ float g_abnout[NA * 2];
__device__ float g_WihT[6 * DIM * G3];   // [sd][k][row]
__device__ float g_WhhT[6 * DIM * G3];   // [sd][k][row]
__device__ int   g_pairs[96][2];         // [scale*32+pair][2], len-matched within scale
__device__ int   g_order[96];            // pair schedule, len desc

__device__ __forceinline__ float sigf(float x) { return 1.f / (1.f + __expf(-x)); }
__device__ __forceinline__ float tanhfast(float x) { return 2.f / (1.f + __expf(-2.f * x)) - 1.f; }

// ---------------- kernel 1 (fused): preprocess + weight transpose ----------------
__global__ void k_pre_tr(const float* __restrict__ emb, const float* __restrict__ tp,
                         const float* __restrict__ pred, const float* __restrict__ al_p,
                         const float* __restrict__ kern,
                         const float* __restrict__ Wih, const float* __restrict__ Whh)
{
    int b = blockIdx.x;
    int t = threadIdx.x;
    if (b < 256) {
        int tid = b * 256 + t;
        if (tid < N_NODES * DIM) {
            int n = tid >> 7, d = tid & 127;
            float freq = (10.f / 127.f) * (float)d;
            g_x[tid] = emb[tid] + 0.05f * sinf(tp[n] * freq);
        }
        if (tid < N_NODES) {
            int n = tid;
            float kv[5];
            #pragma unroll
            for (int k = 0; k < 5; k++) kv[k] = kern[k];
            float sv[5];
            #pragma unroll
            for (int c = 0; c < 5; c++) {
                float acc = 0.f;
                #pragma unroll
                for (int k = 0; k < 5; k++) {
                    int nn = n + k - 2;
                    if (nn >= 0 && nn < N_NODES) acc += kv[k] * pred[nn * 5 + c];
                }
                sv[c] = acc;
            }
            float m = sv[0];
            #pragma unroll
            for (int c = 1; c < 5; c++) m = fmaxf(m, sv[c]);
            float den = 0.f;
            #pragma unroll
            for (int c = 0; c < 5; c++) den += __expf(sv[c] - m);
            g_abn[n] = __expf(sv[0] - m) / den;
            g_tpos[n] = tp[n] * al_p[0];
        }
        return;
    }
    // transpose part
    __shared__ float s1[32][33];
    __shared__ float s2[32][33];
    int bb = b - 256;
    int sd = bb / 48, bx = bb % 48;
    int ktile = bx & 3, rtile = bx >> 2;
    int x = t & 31, y = t >> 5;
    size_t base = (size_t)sd * G3 * DIM;
    #pragma unroll
    for (int j = 0; j < 4; j++) {
        int r = rtile * 32 + y * 4 + j;
        s1[y * 4 + j][x] = Wih[base + (size_t)r * DIM + ktile * 32 + x];
        s2[y * 4 + j][x] = Whh[base + (size_t)r * DIM + ktile * 32 + x];
    }
    __syncthreads();
    size_t obase = (size_t)sd * DIM * G3;
    #pragma unroll
    for (int j = 0; j < 4; j++) {
        int k = ktile * 32 + y * 4 + j;
        g_WihT[obase + (size_t)k * G3 + rtile * 32 + x] = s1[x][y * 4 + j];
        g_WhhT[obase + (size_t)k * G3 + rtile * 32 + x] = s2[x][y * 4 + j];
    }
}

// ---------------- kernel 2: Gi precompute + pair ranking (y==6) ----------------
__global__ __launch_bounds__(384) void k_gi(const float* __restrict__ bih,
                                            const float* __restrict__ anchors)
{
    int t = threadIdx.x;
    if (blockIdx.y == 6) {
        if (blockIdx.x != 0) return;
        __shared__ float tps[N_NODES];
        __shared__ int lens[NA];
        __shared__ int plen[96];
        for (int i = t; i < N_NODES; i += 384) tps[i] = g_tpos[i];
        __syncthreads();
        if (t < NA) {
            float stt = anchors[2 * t], enn = anchors[2 * t + 1];
            int c = 0;
            for (int n = 0; n < N_NODES; n++)
                c += (tps[n] >= stt && tps[n] <= enn) ? 1 : 0;
            lens[t] = c;
        }
        __syncthreads();
        if (t < NA) {
            int s = t >> 6, base = s * 64;
            int L = lens[t];
            int r = 0;
            for (int j = 0; j < 64; j++) {
                int Lj = lens[base + j];
                if (Lj > L || (Lj == L && base + j < t)) r++;
            }
            g_pairs[s * 32 + (r >> 1)][r & 1] = t;
            if ((r & 1) == 0) plen[s * 32 + (r >> 1)] = L;
        }
        __syncthreads();
        if (t < 96) {
            int L = plen[t];
            int g = 0;
            for (int j = 0; j < 96; j++) {
                int Lj = plen[j];
                if (Lj > L || (Lj == L && j < t)) g++;
            }
            g_order[g] = t;
        }
        return;
    }

    int sd = blockIdx.y, chunk = blockIdx.x;
    __shared__ __align__(16) float sx[16 * DIM];
    const float4* src = (const float4*)(g_x + (size_t)chunk * 16 * DIM);
    for (int i = t; i < 16 * DIM / 4; i += 384) ((float4*)sx)[i] = src[i];

    const float* wt = g_WihT + (size_t)sd * DIM * G3 + t;
    ULL w[64];
    #pragma unroll
    for (int k = 0; k < 64; k++) {
        float w0 = wt[(size_t)(2 * k) * G3];
        float w1 = wt[(size_t)(2 * k + 1) * G3];
        asm("mov.b64 %0,{%1,%2};" : "=l"(w[k]) : "f"(w0), "f"(w1));
    }
    float b = bih[sd * G3 + t];
    unsigned xb;
    asm("{.reg .u64 t0; cvta.to.shared.u64 t0,%1; cvt.u32.u64 %0,t0;}" : "=r"(xb) : "l"((float*)sx));
    __syncthreads();

    float* outp = g_Gi + ((size_t)sd * N_NODES + chunk * 16) * G3 + t;
    #pragma unroll 2
    for (int n = 0; n < 16; n++) {
        ULL acA = 0ull, acB = 0ull;
        unsigned base = xb + n * 512;
        #pragma unroll
        for (int i = 0; i < 16; i++) {
            ULL p0, p1, p2, p3;
            asm volatile("ld.shared.v2.b64 {%0,%1},[%2];" : "=l"(p0), "=l"(p1) : "r"(base + i * 32));
            asm volatile("ld.shared.v2.b64 {%0,%1},[%2];" : "=l"(p2), "=l"(p3) : "r"(base + i * 32 + 16));
            asm("fma.rn.f32x2 %0,%1,%2,%0;" : "+l"(acA) : "l"(w[4 * i])     , "l"(p0));
            asm("fma.rn.f32x2 %0,%1,%2,%0;" : "+l"(acB) : "l"(w[4 * i + 1]) , "l"(p1));
            asm("fma.rn.f32x2 %0,%1,%2,%0;" : "+l"(acA) : "l"(w[4 * i + 2]) , "l"(p2));
            asm("fma.rn.f32x2 %0,%1,%2,%0;" : "+l"(acB) : "l"(w[4 * i + 3]) , "l"(p3));
        }
        float a0, a1, b0, b1;
        asm("mov.b64 {%0,%1},%2;" : "=f"(a0), "=f"(a1) : "l"(acA));
        asm("mov.b64 {%0,%1},%2;" : "=f"(b0), "=f"(b1) : "l"(acB));
        outp[(size_t)n * G3] = ((a0 + a1) + (b0 + b1)) + b;
    }
}

// ---------------- kernel 3: GRU, 2 len-matched anchors/block, 4 acc chains ----------------
__global__ __launch_bounds__(384, 1) void k_gru(const float* __restrict__ anchors,
                                                const float* __restrict__ bhh,
                                                const float* __restrict__ aWih,
                                                const float* __restrict__ aWhh,
                                                const float* __restrict__ abih,
                                                const float* __restrict__ abhh)
{
    int t = threadIdx.x;
    __shared__ int sh_task[4];
    __shared__ __align__(16) float sh_h[2][DIM];
    __shared__ float ghA[G3];
    __shared__ float ghB[G3];
    __shared__ unsigned short idxAB[2][N_NODES];
    __shared__ int sh_len[2];
    __shared__ float sh_abh[2];
    __shared__ float aw[12];

    if (t == 0) {
        int pr = g_order[blockIdx.x >> 1];
        sh_task[0] = g_pairs[pr][0];
        sh_task[1] = g_pairs[pr][1];
        sh_task[2] = pr >> 5;
        sh_task[3] = blockIdx.x & 1;
    }
    __syncthreads();
    int aA = sh_task[0], aB = sh_task[1], s = sh_task[2], dir = sh_task[3];
    int sd = s * 2 + dir;

    int wid = t >> 5, lane = t & 31;
    if (wid < 2) {
        int aa = wid ? aB : aA;
        float stt = anchors[2 * aa], enn = anchors[2 * aa + 1];
        unsigned short* ix = idxAB[wid];
        int off = 0;
        for (int base = 0; base < N_NODES; base += 32) {
            int n = base + lane;
            float tp = g_tpos[n];
            bool m = (tp >= stt) && (tp <= enn);
            unsigned bal = __ballot_sync(0xffffffffu, m);
            if (m) ix[off + __popc(bal & ((1u << lane) - 1u))] = (unsigned short)n;
            off += __popc(bal);
        }
        if (dir) {
            for (int i = lane; i < (off >> 1); i += 32) {
                unsigned short tmp = ix[i];
                ix[i] = ix[off - 1 - i];
                ix[off - 1 - i] = tmp;
            }
        }
        if (lane == 0) { sh_len[wid] = off; sh_abh[wid] = 0.f; }
    }
    if (t < DIM) { sh_h[0][t] = 0.f; sh_h[1][t] = 0.f; }
    {
        int base = sd * 3;
        if (t >= 64 && t < 67)  aw[t - 64]      = aWih[base + t - 64];
        if (t >= 67 && t < 70)  aw[3 + t - 67]  = aWhh[base + t - 67];
        if (t >= 70 && t < 73)  aw[6 + t - 70]  = abih[base + t - 70];
        if (t >= 73 && t < 76)  aw[9 + t - 73]  = abhh[base + t - 73];
    }

    const float* wt = g_WhhT + (size_t)sd * DIM * G3 + t;
    ULL w[64];
    #pragma unroll
    for (int k = 0; k < 64; k++) {
        float w0 = wt[(size_t)(2 * k) * G3];
        float w1 = wt[(size_t)(2 * k + 1) * G3];
        asm("mov.b64 %0,{%1,%2};" : "=l"(w[k]) : "f"(w0), "f"(w1));
    }
    float bh = bhh[sd * G3 + t];

    unsigned hb;
    asm("{.reg .u64 t0; cvta.to.shared.u64 t0,%1; cvt.u32.u64 %0,t0;}" : "=r"(hb) : "l"(&sh_h[0][0]));
    __syncthreads();

    int lenA = sh_len[0], lenB = sh_len[1];
    int L = lenA > lenB ? lenA : lenB;
    const float* Gi = g_Gi + (size_t)sd * N_NODES * G3;

    bool roleA = (t < 128);
    bool roleB = (t >= 128 && t < 256);
    int tt = t & 127;
    int mylen = roleA ? lenA : (roleB ? lenB : 0);
    const unsigned short* myidx = roleA ? idxAB[0] : idxAB[1];

    float c0 = 0.f, c1 = 0.f, c2 = 0.f;
    if ((roleA || roleB) && mylen > 0) {
        const float* gp = Gi + (size_t)myidx[0] * G3;
        c0 = gp[tt]; c1 = gp[DIM + tt]; c2 = gp[2 * DIM + tt];
    }
    float abc = 0.f;
    if (t == 256 && lenA > 0) abc = g_abn[idxAB[0][0]];
    if (t == 257 && lenB > 0) abc = g_abn[idxAB[1][0]];

    for (int step = 0; step < L; step++) {
        float n0 = 0.f, n1 = 0.f, n2 = 0.f, abn_next = 0.f;
        int sn = step + 1;
        if ((roleA || roleB) && sn < mylen) {
            const float* gp = Gi + (size_t)myidx[sn] * G3;
            n0 = gp[tt]; n1 = gp[DIM + tt]; n2 = gp[2 * DIM + tt];
        }
        if (t == 256 && sn < lenA) abn_next = g_abn[idxAB[0][sn]];
        if (t == 257 && sn < lenB) abn_next = g_abn[idxAB[1][sn]];

        ULL accA0 = 0ull, accA1 = 0ull, accB0 = 0ull, accB1 = 0ull;
        #pragma unroll
        for (int i = 0; i < 32; i++) {
            ULL a0, a1, b0, b1;
            asm volatile("ld.shared.v2.b64 {%0,%1},[%2];" : "=l"(a0), "=l"(a1) : "r"(hb + i * 16));
            asm volatile("ld.shared.v2.b64 {%0,%1},[%2];" : "=l"(b0), "=l"(b1) : "r"(hb + 512 + i * 16));
            asm("fma.rn.f32x2 %0,%1,%2,%0;" : "+l"(accA0) : "l"(w[2 * i])     , "l"(a0));
            asm("fma.rn.f32x2 %0,%1,%2,%0;" : "+l"(accB0) : "l"(w[2 * i])     , "l"(b0));
            asm("fma.rn.f32x2 %0,%1,%2,%0;" : "+l"(accA1) : "l"(w[2 * i + 1]) , "l"(a1));
            asm("fma.rn.f32x2 %0,%1,%2,%0;" : "+l"(accB1) : "l"(w[2 * i + 1]) , "l"(b1));
        }
        float pa0, pa1, pa2, pa3, pb0, pb1, pb2, pb3;
        asm("mov.b64 {%0,%1},%2;" : "=f"(pa0), "=f"(pa1) : "l"(accA0));
        asm("mov.b64 {%0,%1},%2;" : "=f"(pa2), "=f"(pa3) : "l"(accA1));
        asm("mov.b64 {%0,%1},%2;" : "=f"(pb0), "=f"(pb1) : "l"(accB0));
        asm("mov.b64 {%0,%1},%2;" : "=f"(pb2), "=f"(pb3) : "l"(accB1));
        ghA[t] = ((pa0 + pa1) + (pa2 + pa3)) + bh;
        ghB[t] = ((pb0 + pb1) + (pb2 + pb3)) + bh;
        __syncthreads();

        bool actA = step < lenA, actB = step < lenB;
        if (roleA) {
            if (actA) {
                float r  = sigf(c0 + ghA[tt]);
                float z  = sigf(c1 + ghA[DIM + tt]);
                float nn = tanhfast(c2 + r * ghA[2 * DIM + tt]);
                sh_h[0][tt] = (1.f - z) * nn + z * sh_h[0][tt];
            }
        } else if (roleB) {
            if (actB) {
                float r  = sigf(c0 + ghB[tt]);
                float z  = sigf(c1 + ghB[DIM + tt]);
                float nn = tanhfast(c2 + r * ghB[2 * DIM + tt]);
                sh_h[1][tt] = (1.f - z) * nn + z * sh_h[1][tt];
            }
        } else if (t == 256) {
            if (actA) {
                float h = sh_abh[0];
                float r  = sigf(aw[0] * abc + aw[6] + aw[3] * h + aw[9]);
                float z  = sigf(aw[1] * abc + aw[7] + aw[4] * h + aw[10]);
                float nn = tanhfast(aw[2] * abc + aw[8] + r * (aw[5] * h + aw[11]));
                sh_abh[0] = (1.f - z) * nn + z * h;
            }
        } else if (t == 257) {
            if (actB) {
                float h = sh_abh[1];
                float r  = sigf(aw[0] * abc + aw[6] + aw[3] * h + aw[9]);
                float z  = sigf(aw[1] * abc + aw[7] + aw[4] * h + aw[10]);
                float nn = tanhfast(aw[2] * abc + aw[8] + r * (aw[5] * h + aw[11]));
                sh_abh[1] = (1.f - z) * nn + z * h;
            }
        }
        c0 = n0; c1 = n1; c2 = n2; abc = abn_next;
        __syncthreads();
    }

    if (roleA)      g_hout[((size_t)aA * 2 + dir) * DIM + tt] = sh_h[0][tt];
    else if (roleB) g_hout[((size_t)aB * 2 + dir) * DIM + tt] = sh_h[1][tt];
    else if (t == 256) g_abnout[aA * 2 + dir] = sh_abh[0];
    else if (t == 257) g_abnout[aB * 2 + dir] = sh_abh[1];
}

// ---------------- kernel 4: MLP head, 1 anchor/block, 64-deep front-batched loads ----------------
__global__ __launch_bounds__(256) void k_head(const float* __restrict__ anchors,
                                              const float* __restrict__ al_p,
                                              const float* __restrict__ W1, const float* __restrict__ b1,
                                              const float* __restrict__ W2, const float* __restrict__ b2,
                                              const float* __restrict__ W3, const float* __restrict__ b3,
                                              const float* __restrict__ start_w,
                                              const float* __restrict__ end_w,
                                              float* __restrict__ out)
{
    int a = blockIdx.x;
    int s = a >> 6;
    int t = threadIdx.x;
    const int FIN = 2 * DIM + 3;   // 259
    const int FOUT = 47;

    __shared__ float sf[FIN + 1];
    __shared__ float h1[256];
    __shared__ float h2[256];
    __shared__ float o[FOUT + 1];
    __shared__ float soeo[2];

    float al = al_p[0];
    if (t < DIM) {
        sf[t]       = g_hout[((size_t)a * 2 + 0) * DIM + t];
        sf[DIM + t] = g_hout[((size_t)a * 2 + 1) * DIM + t];
    }
    if (t == 0) {
        sf[256] = 0.5f * (g_abnout[a * 2] + g_abnout[a * 2 + 1]);
        float stt = anchors[a * 2], enn = anchors[a * 2 + 1];
        sf[257] = (stt + enn) * 0.5f / al;
        sf[258] = (enn - stt) / al;
    }
    __syncthreads();

    // layer 1: 4 phases of 64 front-batched loads -> 8 acc chains
    {
        const float* W = W1 + (size_t)s * FIN * 256 + t;
        float acc[8];
        #pragma unroll
        for (int q = 0; q < 8; q++) acc[q] = 0.f;
        float wreg[64];
        #pragma unroll
        for (int p = 0; p < 4; p++) {
            int i0 = p * 64;
            #pragma unroll
            for (int j = 0; j < 64; j++) wreg[j] = W[(size_t)(i0 + j) * 256];
            #pragma unroll
            for (int j = 0; j < 64; j++) acc[j & 7] += wreg[j] * sf[i0 + j];
        }
        acc[0] += W[(size_t)256 * 256] * sf[256];
        acc[1] += W[(size_t)257 * 256] * sf[257];
        acc[2] += W[(size_t)258 * 256] * sf[258];
        float r = (((acc[0] + acc[1]) + (acc[2] + acc[3])) + ((acc[4] + acc[5]) + (acc[6] + acc[7])))
                  + b1[s * 256 + t];
        h1[t] = fmaxf(r, 0.f);
    }
    __syncthreads();

    // layer 2
    {
        const float* W = W2 + (size_t)s * 256 * 256 + t;
        float acc[8];
        #pragma unroll
        for (int q = 0; q < 8; q++) acc[q] = 0.f;
        float wreg[64];
        #pragma unroll
        for (int p = 0; p < 4; p++) {
            int i0 = p * 64;
            #pragma unroll
            for (int j = 0; j < 64; j++) wreg[j] = W[(size_t)(i0 + j) * 256];
            #pragma unroll
            for (int j = 0; j < 64; j++) acc[j & 7] += wreg[j] * h1[i0 + j];
        }
        float r = (((acc[0] + acc[1]) + (acc[2] + acc[3])) + ((acc[4] + acc[5]) + (acc[6] + acc[7])))
                  + b2[s * 256 + t];
        h2[t] = fmaxf(r, 0.f);
    }
    __syncthreads();

    // layer 3 (47 outputs)
    if (t < FOUT) {
        const float* W = W3 + (size_t)s * 256 * FOUT + t;
        float acc[8];
        #pragma unroll
        for (int q = 0; q < 8; q++) acc[q] = 0.f;
        float wreg[64];
        #pragma unroll
        for (int p = 0; p < 4; p++) {
            int i0 = p * 64;
            #pragma unroll
            for (int j = 0; j < 64; j++) wreg[j] = W[(size_t)(i0 + j) * FOUT];
            #pragma unroll
            for (int j = 0; j < 64; j++) acc[j & 7] += wreg[j] * h2[i0 + j];
        }
        o[t] = (((acc[0] + acc[1]) + (acc[2] + acc[3])) + ((acc[4] + acc[5]) + (acc[6] + acc[7])))
               + b3[s * FOUT + t];
    }
    __syncthreads();

    if (t < 2) {
        const float* wv = (t == 0) ? (start_w + s * 21) : (end_w + s * 21);
        const float* ov = o + t * 21;
        float m = -1e30f;
        for (int j = 0; j < 21; j++) m = fmaxf(m, ov[j]);
        float den = 0.f, num = 0.f;
        for (int j = 0; j < 21; j++) { float e = __expf(ov[j] - m); den += e; num += e * wv[j]; }
        soeo[t] = num / den;
    }
    __syncthreads();

    if (t == 0) {
        float stt = anchors[a * 2], enn = anchors[a * 2 + 1];
        out[a * 2]      = fminf(fmaxf(stt + soeo[0], 0.f), al);
        out[a * 2 + 1]  = fminf(fmaxf(enn + soeo[1], 0.f), al);
        out[2 * NA + a] = o[42];
    }
    if (t < 4) out[3 * NA + a * 4 + t] = o[43 + t];
}

// ---------------- launcher ----------------
extern "C" void kernel_launch(void* const* d_in, const int* in_sizes, int n_in,
                              void* d_out, int out_size)
{
    const float* emb   = (const float*)d_in[0];
    const float* tp    = (const float*)d_in[1];
    const float* pred  = (const float*)d_in[2];
    const float* al_p  = (const float*)d_in[3];
    const float* anc   = (const float*)d_in[4];
    const float* kern  = (const float*)d_in[5];
    const float* fWih  = (const float*)d_in[6];
    const float* fWhh  = (const float*)d_in[7];
    const float* fbih  = (const float*)d_in[8];
    const float* fbhh  = (const float*)d_in[9];
    const float* aWih  = (const float*)d_in[10];
    const float* aWhh  = (const float*)d_in[11];
    const float* abih  = (const float*)d_in[12];
    const float* abhh  = (const float*)d_in[13];
    const float* sw    = (const float*)d_in[14];
    const float* ew    = (const float*)d_in[15];
    const float* W1    = (const float*)d_in[16];
    const float* b1    = (const float*)d_in[17];
    const float* W2    = (const float*)d_in[18];
    const float* b2    = (const float*)d_in[19];
    const float* W3    = (const float*)d_in[20];
    const float* b3    = (const float*)d_in[21];
    float* outp = (float*)d_out;

    k_pre_tr<<<544, 256>>>(emb, tp, pred, al_p, kern, fWih, fWhh);
    k_gi<<<dim3(32, 7), 384>>>(fbih, anc);
    k_gru<<<NA, 384>>>(anc, fbhh, aWih, aWhh, abih, abhh);
    k_head<<<NA, 256>>>(anc, al_p, W1, b1, W2, b2, W3, b3, sw, ew, outp);
}